// round 10
// baseline (speedup 1.0000x reference)
#include <cuda_runtime.h>
#include <cuda_bf16.h>
#include <math.h>
#include <stdint.h>

// ---------------- problem constants ----------------
#define BATCH 64
#define NTOK  785          // 1 + 28*28
#define CH    768
#define NH    12
#define HD    64
#define AG    49
#define WIN   28
#define SCALE 0.125f       // hd^-0.5

// ---------------- scratch (device globals; no allocs allowed) ----------------
__device__ __align__(16) float g_qkv[(size_t)BATCH * NTOK * 3 * CH];   // (B,N,3C)
__device__ __align__(16) float g_agent[(size_t)BATCH * AG * CH];       // (B,A,C)
__device__ __align__(16) float g_agentv[(size_t)BATCH * NH * AG * HD]; // (B,H,A,hd)
__device__ __align__(16) float g_attn[(size_t)BATCH * NTOK * CH];      // pre-proj output
__device__ __align__(16) float g_pos1[(size_t)NH * AG * NTOK];         // (H,A,N)
__device__ __align__(16) float g_pos2[(size_t)NH * NTOK * AG];         // (H,N,A)
__device__ __align__(16) float g_s1[(size_t)BATCH * NH * AG * NTOK];   // stage-1 raw scores

// bf16 three-term split buffers (K tripled: 768 -> 2304)
// per original k: A' = {hi_a, lo_a, hi_a},  W' = {hi_w, hi_w, lo_w}
// => dot = hi*hi + lo_a*hi_w + hi_a*lo_w  (drops only lo*lo ~ 2^-18)
#define KT 2304
__device__ __align__(16) __nv_bfloat16 g_xs[(size_t)BATCH * NTOK * KT];   // x split (A pattern)
__device__ __align__(16) __nv_bfloat16 g_as[(size_t)BATCH * NTOK * KT];   // attn split (A pattern)
__device__ __align__(16) __nv_bfloat16 g_wqs[(size_t)(3 * CH) * KT];      // w_qkv split (W pattern)
__device__ __align__(16) __nv_bfloat16 g_wps[(size_t)CH * KT];            // w_proj split (W pattern)

// ================= PTX helpers (baseline ISA only: sm_80-class) =================
__device__ __forceinline__ uint32_t smem_u32(const void* p) {
    uint32_t a;
    asm("{ .reg .u64 t; cvta.to.shared.u64 t, %1; cvt.u32.u64 %0, t; }"
        : "=r"(a) : "l"(p));
    return a;
}
__device__ __forceinline__ void cpasync16(uint32_t dst, const void* src) {
    asm volatile("cp.async.cg.shared.global [%0], [%1], 16;" :: "r"(dst), "l"(src));
}
__device__ __forceinline__ void cpasync_commit() {
    asm volatile("cp.async.commit_group;" ::: "memory");
}
template <int N>
__device__ __forceinline__ void cpasync_wait() {
    asm volatile("cp.async.wait_group %0;" :: "n"(N) : "memory");
}
__device__ __forceinline__ void ldsm4(uint32_t* r, uint32_t addr) {
    asm volatile("ldmatrix.sync.aligned.m8n8.x4.shared.b16 {%0,%1,%2,%3}, [%4];"
                 : "=r"(r[0]), "=r"(r[1]), "=r"(r[2]), "=r"(r[3]) : "r"(addr));
}
__device__ __forceinline__ void mma16816(float* c, const uint32_t* a,
                                         uint32_t b0, uint32_t b1) {
    asm volatile(
        "mma.sync.aligned.m16n8k16.row.col.f32.bf16.bf16.f32 "
        "{%0,%1,%2,%3}, {%4,%5,%6,%7}, {%8,%9}, {%0,%1,%2,%3};"
        : "+f"(c[0]), "+f"(c[1]), "+f"(c[2]), "+f"(c[3])
        : "r"(a[0]), "r"(a[1]), "r"(a[2]), "r"(a[3]), "r"(b0), "r"(b1));
}

// ================= three-term splits =================
union Pack24 {
    __nv_bfloat16 h[24];
    uint4 q[3];
};

__global__ __launch_bounds__(256) void split3_a(
    const float* __restrict__ src, __nv_bfloat16* __restrict__ dst, int n8)
{
    int i = blockIdx.x * 256 + threadIdx.x;
    if (i >= n8) return;
    float4 v0 = ((const float4*)src)[2 * i];
    float4 v1 = ((const float4*)src)[2 * i + 1];
    float f[8] = {v0.x, v0.y, v0.z, v0.w, v1.x, v1.y, v1.z, v1.w};
    Pack24 o;
#pragma unroll
    for (int j = 0; j < 8; j++) {
        __nv_bfloat16 hi = __float2bfloat16(f[j]);
        __nv_bfloat16 lo = __float2bfloat16(f[j] - __bfloat162float(hi));
        o.h[3 * j] = hi; o.h[3 * j + 1] = lo; o.h[3 * j + 2] = hi;
    }
    uint4* d = (uint4*)(dst + (size_t)24 * i);
    d[0] = o.q[0]; d[1] = o.q[1]; d[2] = o.q[2];
}

__global__ __launch_bounds__(256) void split3_w(
    const float* __restrict__ src, __nv_bfloat16* __restrict__ dst, int n8)
{
    int i = blockIdx.x * 256 + threadIdx.x;
    if (i >= n8) return;
    float4 v0 = ((const float4*)src)[2 * i];
    float4 v1 = ((const float4*)src)[2 * i + 1];
    float f[8] = {v0.x, v0.y, v0.z, v0.w, v1.x, v1.y, v1.z, v1.w};
    Pack24 o;
#pragma unroll
    for (int j = 0; j < 8; j++) {
        __nv_bfloat16 hi = __float2bfloat16(f[j]);
        __nv_bfloat16 lo = __float2bfloat16(f[j] - __bfloat162float(hi));
        o.h[3 * j] = hi; o.h[3 * j + 1] = hi; o.h[3 * j + 2] = lo;
    }
    uint4* d = (uint4*)(dst + (size_t)24 * i);
    d[0] = o.q[0]; d[1] = o.q[1]; d[2] = o.q[2];
}

// ================= bf16-split tensor-core GEMM (mma.sync, 256x128 tile) =================
// C[m,n] = sum_k A'[m,k]*B'[n,k] (+bias[n]); A': M x KT bf16, B': Nw x KT bf16
#define KC 32                        // bf16 k per chunk
#define NCHUNK (KT / KC)             // 72
#define AST 40                       // padded smem row stride (bf16)
#define A_BYTES (256 * AST * 2)      // 20480 per stage
#define STAGE_BYTES ((256 + 128) * AST * 2)   // 30720
#define NSTAGE 3
#define GEMM_DSM (NSTAGE * STAGE_BYTES)       // 92160

__global__ __launch_bounds__(512) void gemm_mma(
    const __nv_bfloat16* __restrict__ A, const __nv_bfloat16* __restrict__ Bw,
    const float* __restrict__ bias, float* __restrict__ C,
    int M, int Nw)
{
    extern __shared__ char dsm[];
    const uint32_t su = smem_u32(dsm);

    const int ntiles = Nw >> 7;
    const int m0 = (blockIdx.x / ntiles) << 8;
    const int n0 = (blockIdx.x % ntiles) << 7;
    const int tid = threadIdx.x;
    const int wid = tid >> 5, lane = tid & 31;
    const int wm = wid & 3, wn = wid >> 2;      // 4 x 4 warp grid; warp tile 64x32

    // ---- cp.async mapping ----
    // A: 256 rows x 64B -> 1024 16B chunks -> 2 per thread
    const __nv_bfloat16* Ag[2];
    uint32_t soA[2];
#pragma unroll
    for (int i = 0; i < 2; i++) {
        int idx = tid + 512 * i;
        int row = idx >> 2, c = idx & 3;
        Ag[i] = A + (size_t)min(m0 + row, M - 1) * KT + c * 8;
        soA[i] = (uint32_t)(row * AST + c * 8) * 2;
    }
    // B: 128 rows x 64B -> 512 chunks -> 1 per thread
    const __nv_bfloat16* Bg;
    uint32_t soB;
    {
        int row = tid >> 2, c = tid & 3;
        Bg = Bw + (size_t)(n0 + row) * KT + c * 8;
        soB = (uint32_t)A_BYTES + (uint32_t)(row * AST + c * 8) * 2;
    }

    // prologue: stages 0..1
#pragma unroll
    for (int s = 0; s < NSTAGE - 1; s++) {
        uint32_t st = su + s * STAGE_BYTES;
        int ko = s * KC;
        cpasync16(st + soA[0], Ag[0] + ko);
        cpasync16(st + soA[1], Ag[1] + ko);
        cpasync16(st + soB, Bg + ko);
        cpasync_commit();
    }

    float acc[4][4][4];
#pragma unroll
    for (int mt = 0; mt < 4; mt++)
#pragma unroll
        for (int nt = 0; nt < 4; nt++)
#pragma unroll
            for (int q = 0; q < 4; q++) acc[mt][nt][q] = 0.f;

    const int lrow16 = lane & 15;
    const int lk8 = (lane >> 4) << 3;

    for (int c = 0; c < NCHUNK; c++) {
        cpasync_wait<NSTAGE - 2>();
        __syncthreads();
        int pf = c + NSTAGE - 1;
        if (pf < NCHUNK) {
            uint32_t st = su + (pf % NSTAGE) * STAGE_BYTES;
            int ko = pf * KC;
            cpasync16(st + soA[0], Ag[0] + ko);
            cpasync16(st + soA[1], Ag[1] + ko);
            cpasync16(st + soB, Bg + ko);
        }
        cpasync_commit();

        const uint32_t sb = su + (c % NSTAGE) * STAGE_BYTES;
#pragma unroll
        for (int ks = 0; ks < 2; ks++) {
            uint32_t af[4][4];
#pragma unroll
            for (int mt = 0; mt < 4; mt++)
                ldsm4(af[mt], sb + (uint32_t)(((wm * 64 + mt * 16 + lrow16) * AST)
                                              + ks * 16 + lk8) * 2);
            uint32_t bf[2][4];
#pragma unroll
            for (int nt2 = 0; nt2 < 2; nt2++)
                ldsm4(bf[nt2], sb + A_BYTES
                      + (uint32_t)(((wn * 32 + nt2 * 16 + lrow16) * AST)
                                   + ks * 16 + lk8) * 2);
#pragma unroll
            for (int mt = 0; mt < 4; mt++)
#pragma unroll
                for (int nt2 = 0; nt2 < 2; nt2++) {
                    mma16816(acc[mt][nt2 * 2 + 0], af[mt], bf[nt2][0], bf[nt2][2]);
                    mma16816(acc[mt][nt2 * 2 + 1], af[mt], bf[nt2][1], bf[nt2][3]);
                }
        }
    }

    // ---- epilogue ----
#pragma unroll
    for (int mt = 0; mt < 4; mt++) {
        int r0 = m0 + wm * 64 + mt * 16 + (lane >> 2);
        int r1 = r0 + 8;
#pragma unroll
        for (int j = 0; j < 4; j++) {
            int col = n0 + wn * 32 + j * 8 + (lane & 3) * 2;
            float b0 = 0.f, b1 = 0.f;
            if (bias) { b0 = bias[col]; b1 = bias[col + 1]; }
            if (r0 < M) {
                float2 o; o.x = acc[mt][j][0] + b0; o.y = acc[mt][j][1] + b1;
                *(float2*)(C + (size_t)r0 * Nw + col) = o;
            }
            if (r1 < M) {
                float2 o; o.x = acc[mt][j][2] + b0; o.y = acc[mt][j][3] + b1;
                *(float2*)(C + (size_t)r1 * Nw + col) = o;
            }
        }
    }
}

// ---------------- agent pooling: 28x28 q image tokens -> 7x7 avg ----------------
__global__ __launch_bounds__(256) void pool_agent(float* __restrict__ agent)
{
    const int a = blockIdx.x;
    const int b = blockIdx.y;
    const int pr = a / 7, pc = a % 7;
    for (int c = threadIdx.x; c < CH; c += 256) {
        float s = 0.f;
#pragma unroll
        for (int i = 0; i < 4; i++)
#pragma unroll
            for (int j = 0; j < 4; j++) {
                int tok = 1 + (pr * 4 + i) * WIN + (pc * 4 + j);
                s += g_qkv[((size_t)(b * NTOK + tok)) * (3 * CH) + c];
            }
        agent[((size_t)b * AG + a) * CH + c] = s * (1.f / 16.f);
    }
}

// ---------------- jax bilinear (half-pixel upsample => clamped bilinear) ----------------
__device__ __forceinline__ float bilin7(const float* __restrict__ p, int r, int c)
{
    float fy = (r + 0.5f) * 0.25f - 0.5f;
    float fx = (c + 0.5f) * 0.25f - 0.5f;
    int y0 = (int)floorf(fy); float wy = fy - (float)y0;
    int x0 = (int)floorf(fx); float wx = fx - (float)x0;
    int y0c = min(max(y0, 0), 6), y1c = min(max(y0 + 1, 0), 6);
    int x0c = min(max(x0, 0), 6), x1c = min(max(x0 + 1, 0), 6);
    float v00 = p[y0c * 7 + x0c], v01 = p[y0c * 7 + x1c];
    float v10 = p[y1c * 7 + x0c], v11 = p[y1c * 7 + x1c];
    return (1.f - wy) * ((1.f - wx) * v00 + wx * v01)
         + wy * ((1.f - wx) * v10 + wx * v11);
}

__global__ __launch_bounds__(256) void build_pos1(
    const float* __restrict__ an, const float* __restrict__ ah,
    const float* __restrict__ aw, const float* __restrict__ ac)
{
    const int h = blockIdx.x / AG, a = blockIdx.x % AG;
    const float* anp = an + ((size_t)h * AG + a) * 49;
    float* out = g_pos1 + ((size_t)h * AG + a) * NTOK;
    if (threadIdx.x == 0) out[0] = ac[h * AG + a];
    for (int t = threadIdx.x; t < WIN * WIN; t += 256) {
        int r = t / WIN, c = t % WIN;
        out[1 + t] = bilin7(anp, r, c)
                   + ah[((size_t)h * AG + a) * WIN + r]
                   + aw[((size_t)h * AG + a) * WIN + c];
    }
}

__global__ __launch_bounds__(64) void build_pos2(
    const float* __restrict__ na, const float* __restrict__ ha,
    const float* __restrict__ wa, const float* __restrict__ ca)
{
    const int n = blockIdx.x;
    const int h = blockIdx.y;
    const int a = threadIdx.x;
    if (a >= AG) return;
    float v;
    if (n == 0) {
        v = ca[h * AG + a];
    } else {
        int t = n - 1, r = t / WIN, c = t % WIN;
        v = bilin7(na + ((size_t)h * AG + a) * 49, r, c)
          + ha[(size_t)h * WIN * AG + (size_t)r * AG + a]
          + wa[(size_t)h * WIN * AG + (size_t)c * AG + a];
    }
    g_pos2[((size_t)h * NTOK + n) * AG + a] = v;
}

// ---------------- stage 1: scores = scale*agent @ k^T + pos1 (raw, no softmax) ----------------
__global__ __launch_bounds__(256) void s1_scores(const float* __restrict__ agent)
{
    const int b = blockIdx.x / NH, h = blockIdx.x % NH;
    __shared__ __align__(16) float agt[AG][HD];
    for (int i = threadIdx.x; i < AG * HD; i += 256) {
        int a = i / HD, d = i % HD;
        agt[a][d] = agent[((size_t)b * AG + a) * CH + h * HD + d] * SCALE;
    }
    __syncthreads();
    const float* pb = g_pos1 + (size_t)h * AG * NTOK;
    for (int n = threadIdx.x; n < NTOK; n += 256) {
        const float* kp = g_qkv + ((size_t)(b * NTOK + n)) * (3 * CH) + CH + h * HD;
        float kr[HD];
#pragma unroll
        for (int d = 0; d < HD; d += 4) {
            float4 t = *(const float4*)(kp + d);
            kr[d] = t.x; kr[d + 1] = t.y; kr[d + 2] = t.z; kr[d + 3] = t.w;
        }
        float* sout = g_s1 + ((size_t)(b * NH + h)) * AG * NTOK + n;
#pragma unroll 1
        for (int a = 0; a < AG; a++) {
            const float4* ap = (const float4*)agt[a];
            float acc = 0.f;
#pragma unroll
            for (int q = 0; q < HD / 4; q++) {
                float4 av = ap[q];
                acc += av.x * kr[4 * q] + av.y * kr[4 * q + 1]
                     + av.z * kr[4 * q + 2] + av.w * kr[4 * q + 3];
            }
            sout[(size_t)a * NTOK] = acc + pb[(size_t)a * NTOK + n];
        }
    }
}

// ---------------- stage 1: fused softmax + agent_v = softmax(scores) @ v ----------------
__global__ __launch_bounds__(256) void s1_av()
{
    const int b = blockIdx.x / NH, h = blockIdx.x % NH;
    __shared__ float sv[64][HD];
    __shared__ float sp[AG][64];
    __shared__ float smx[AG], sinv[AG];
    const int tid = threadIdx.x;
    const int wid = tid >> 5, lane = tid & 31;
    const int d  = tid & 63;
    const int a0 = tid >> 6;

    const size_t pbase = ((size_t)(b * NH + h)) * AG * NTOK;
    const float* S = g_s1 + pbase;

    // phase 1: per-agent max & sum (warp per agent)
    for (int a = wid; a < AG; a += 8) {
        const float* row = S + (size_t)a * NTOK;
        float mx = -1e30f;
        for (int n = lane; n < NTOK; n += 32) mx = fmaxf(mx, row[n]);
#pragma unroll
        for (int o = 16; o > 0; o >>= 1)
            mx = fmaxf(mx, __shfl_xor_sync(0xFFFFFFFFu, mx, o));
        float sm = 0.f;
        for (int n = lane; n < NTOK; n += 32) sm += expf(row[n] - mx);
#pragma unroll
        for (int o = 16; o > 0; o >>= 1)
            sm += __shfl_xor_sync(0xFFFFFFFFu, sm, o);
        if (lane == 0) { smx[a] = mx; sinv[a] = 1.f / sm; }
    }
    __syncthreads();

    float acc[13];
#pragma unroll
    for (int i = 0; i < 13; i++) acc[i] = 0.f;

    for (int n0 = 0; n0 < NTOK; n0 += 64) {
        int nt = min(64, NTOK - n0);
        __syncthreads();
        for (int i = tid; i < nt * HD; i += 256) {
            int nn = i >> 6, dd = i & 63;
            sv[nn][dd] = g_qkv[((size_t)(b * NTOK + n0 + nn)) * (3 * CH) + 2 * CH + h * HD + dd];
        }
        for (int i = tid; i < AG * 64; i += 256) {
            int a = i >> 6, nn = i & 63;
            if (nn < nt)
                sp[a][nn] = expf(S[(size_t)a * NTOK + n0 + nn] - smx[a]);
        }
        __syncthreads();
        for (int nn = 0; nn < nt; nn++) {
            float vv = sv[nn][d];
#pragma unroll
            for (int i = 0; i < 13; i++) {
                int a = a0 + 4 * i;
                if (a < AG) acc[i] += sp[a][nn] * vv;
            }
        }
    }
#pragma unroll
    for (int i = 0; i < 13; i++) {
        int a = a0 + 4 * i;
        if (a < AG)
            g_agentv[((size_t)(b * NH + h) * AG + a) * HD + d] = acc[i] * sinv[a];
    }
}

// ---------------- stage 2 fused ----------------
__global__ __launch_bounds__(256) void stage2(const float* __restrict__ agent)
{
    const int h = blockIdx.y, b = blockIdx.z;
    __shared__ __align__(16) float agt[AG][HD];
    __shared__ __align__(16) float sv[AG][HD];
    for (int i = threadIdx.x; i < AG * HD; i += 256) {
        int a = i / HD, d = i % HD;
        agt[a][d] = agent[((size_t)b * AG + a) * CH + h * HD + d] * SCALE;
        sv[a][d]  = g_agentv[((size_t)(b * NH + h) * AG + a) * HD + d];
    }
    __syncthreads();

    const int n = blockIdx.x * 256 + threadIdx.x;
    if (n >= NTOK) return;

    float qr[HD];
    const float* qp = g_qkv + ((size_t)(b * NTOK + n)) * (3 * CH) + h * HD;
#pragma unroll
    for (int dd = 0; dd < HD; dd += 4) {
        float4 t = *(const float4*)(qp + dd);
        qr[dd] = t.x; qr[dd + 1] = t.y; qr[dd + 2] = t.z; qr[dd + 3] = t.w;
    }

    const float* pb = g_pos2 + ((size_t)h * NTOK + n) * AG;
    float sc[AG];
    float mx = -1e30f;
#pragma unroll 1
    for (int a = 0; a < AG; a++) {
        const float4* ap = (const float4*)agt[a];
        float acc = 0.f;
#pragma unroll
        for (int q = 0; q < HD / 4; q++) {
            float4 av = ap[q];
            acc += av.x * qr[4 * q] + av.y * qr[4 * q + 1]
                 + av.z * qr[4 * q + 2] + av.w * qr[4 * q + 3];
        }
        sc[a] = acc + pb[a];
        mx = fmaxf(mx, sc[a]);
    }
    float sum = 0.f;
#pragma unroll
    for (int a = 0; a < AG; a++) {
        float e = expf(sc[a] - mx);
        sc[a] = e; sum += e;
    }
    float inv = 1.f / sum;
#pragma unroll
    for (int a = 0; a < AG; a++) sc[a] *= inv;

    float od[HD];
#pragma unroll
    for (int dd = 0; dd < HD; dd++) od[dd] = 0.f;
#pragma unroll 1
    for (int a = 0; a < AG; a++) {
        float w = sc[a];
        const float4* vp = (const float4*)sv[a];
#pragma unroll
        for (int q = 0; q < HD / 4; q++) {
            float4 t = vp[q];
            od[4 * q]     += w * t.x; od[4 * q + 1] += w * t.y;
            od[4 * q + 2] += w * t.z; od[4 * q + 3] += w * t.w;
        }
    }
    float* op = g_attn + ((size_t)(b * NTOK + n)) * CH + h * HD;
#pragma unroll
    for (int dd = 0; dd < HD; dd += 4) {
        float4 t;
        t.x = od[dd]; t.y = od[dd + 1]; t.z = od[dd + 2]; t.w = od[dd + 3];
        *(float4*)(op + dd) = t;
    }
}

// ---------------- depthwise 3x3 conv on v image tokens ----------------
__global__ __launch_bounds__(256) void dwc_add(
    const float* __restrict__ w, const float* __restrict__ bias)
{
    const int t = blockIdx.x;
    const int b = blockIdx.y;
    const int r = t / WIN, cc = t % WIN;
    for (int c = threadIdx.x; c < CH; c += 256) {
        float acc = bias[c];
#pragma unroll
        for (int ky = 0; ky < 3; ky++) {
            int rr = r + ky - 1;
            if (rr < 0 || rr >= WIN) continue;
#pragma unroll
            for (int kx = 0; kx < 3; kx++) {
                int c2 = cc + kx - 1;
                if (c2 < 0 || c2 >= WIN) continue;
                acc += w[(ky * 3 + kx) * CH + c]
                     * g_qkv[((size_t)(b * NTOK + 1 + rr * WIN + c2)) * (3 * CH) + 2 * CH + c];
            }
        }
        g_attn[((size_t)(b * NTOK + 1 + t)) * CH + c] += acc;
    }
}

// ---------------- launch ----------------
extern "C" void kernel_launch(void* const* d_in, const int* in_sizes, int n_in,
                              void* d_out, int out_size)
{
    const float* x      = (const float*)d_in[0];
    const float* w_qkv  = (const float*)d_in[1];
    const float* w_proj = (const float*)d_in[2];
    const float* b_proj = (const float*)d_in[3];
    const float* dwc_w  = (const float*)d_in[4];
    const float* dwc_b  = (const float*)d_in[5];
    const float* an_b   = (const float*)d_in[6];
    const float* ah_b   = (const float*)d_in[7];
    const float* aw_b   = (const float*)d_in[8];
    const float* na_b   = (const float*)d_in[9];
    const float* ha_b   = (const float*)d_in[10];
    const float* wa_b   = (const float*)d_in[11];
    const float* ac_b   = (const float*)d_in[12];
    const float* ca_b   = (const float*)d_in[13];
    float* out = (float*)d_out;

    float *p_qkv, *p_agent, *p_attn;
    cudaGetSymbolAddress((void**)&p_qkv, g_qkv);
    cudaGetSymbolAddress((void**)&p_agent, g_agent);
    cudaGetSymbolAddress((void**)&p_attn, g_attn);
    __nv_bfloat16 *p_xs, *p_as, *p_wqs, *p_wps;
    cudaGetSymbolAddress((void**)&p_xs, g_xs);
    cudaGetSymbolAddress((void**)&p_as, g_as);
    cudaGetSymbolAddress((void**)&p_wqs, g_wqs);
    cudaGetSymbolAddress((void**)&p_wps, g_wps);

    cudaFuncSetAttribute(gemm_mma, cudaFuncAttributeMaxDynamicSharedMemorySize,
                         GEMM_DSM);

    const int M = BATCH * NTOK;              // 50240
    const int MTILES = (M + 255) / 256;      // 197

    // 0) three-term bf16 splits of x and weights
    const int x8 = M * CH / 8;
    split3_a<<<(x8 + 255) / 256, 256>>>(x, p_xs, x8);
    const int wq8 = 3 * CH * CH / 8;
    split3_w<<<(wq8 + 255) / 256, 256>>>(w_qkv, p_wqs, wq8);
    const int wp8 = CH * CH / 8;
    split3_w<<<(wp8 + 255) / 256, 256>>>(w_proj, p_wps, wp8);

    // 1) QKV GEMM on tensor cores (mma.sync, 256x128 tiles, 3-stage)
    gemm_mma<<<MTILES * (3 * CH / 128), 512, GEMM_DSM>>>(
        p_xs, p_wqs, nullptr, p_qkv, M, 3 * CH);

    // 2) agent pooling
    pool_agent<<<dim3(AG, BATCH), 256>>>(p_agent);

    // 3/4) position biases
    build_pos1<<<NH * AG, 256>>>(an_b, ah_b, aw_b, ac_b);
    build_pos2<<<dim3(NTOK, NH), 64>>>(na_b, ha_b, wa_b, ca_b);

    // 5) stage-1 scores, fused softmax+AV
    s1_scores<<<BATCH * NH, 256>>>(p_agent);
    s1_av<<<BATCH * NH, 256>>>();

    // 6) stage-2 fused attention
    stage2<<<dim3((NTOK + 255) / 256, NH, BATCH), 256>>>(p_agent);

    // 7) depthwise conv add
    dwc_add<<<dim3(WIN * WIN, BATCH), 256>>>(dwc_w, dwc_b);

    // 8) output projection on tensor cores (split attn first)
    split3_a<<<(x8 + 255) / 256, 256>>>(p_attn, p_as, x8);
    gemm_mma<<<MTILES * (CH / 128), 512, GEMM_DSM>>>(
        p_as, p_wps, b_proj, out, M, CH);
}

// round 11
// speedup vs baseline: 1.0842x; 1.0842x over previous
#include <cuda_runtime.h>
#include <cuda_bf16.h>
#include <math.h>
#include <stdint.h>

// ---------------- problem constants ----------------
#define BATCH 64
#define NTOK  785          // 1 + 28*28
#define CH    768
#define NH    12
#define HD    64
#define AG    49
#define WIN   28
#define SCALE 0.125f       // hd^-0.5

// ---------------- scratch (device globals; no allocs allowed) ----------------
__device__ __align__(16) float g_qkv[(size_t)BATCH * NTOK * 3 * CH];   // (B,N,3C)
__device__ __align__(16) float g_agent[(size_t)BATCH * AG * CH];       // (B,A,C)
__device__ __align__(16) float g_agentv[(size_t)BATCH * NH * AG * HD]; // (B,H,A,hd)
__device__ __align__(16) float g_attn[(size_t)BATCH * NTOK * CH];      // pre-proj output
__device__ __align__(16) float g_pos1[(size_t)NH * AG * NTOK];         // (H,A,N)
__device__ __align__(16) float g_pos2[(size_t)NH * NTOK * AG];         // (H,N,A)
__device__ __align__(16) float g_s1[(size_t)BATCH * NH * AG * NTOK];   // stage-1 raw scores

// bf16 three-term split buffers (K tripled: 768 -> 2304)
// per original k: A' = {hi_a, lo_a, hi_a},  W' = {hi_w, hi_w, lo_w}
// => dot = hi*hi + lo_a*hi_w + hi_a*lo_w  (drops only lo*lo ~ 2^-18)
#define KT 2304
__device__ __align__(16) __nv_bfloat16 g_xs[(size_t)BATCH * NTOK * KT];   // x split (A pattern)
__device__ __align__(16) __nv_bfloat16 g_as[(size_t)BATCH * NTOK * KT];   // attn split (A pattern)
__device__ __align__(16) __nv_bfloat16 g_wqs[(size_t)(3 * CH) * KT];      // w_qkv split (W pattern)
__device__ __align__(16) __nv_bfloat16 g_wps[(size_t)CH * KT];            // w_proj split (W pattern)

// ================= PTX helpers (baseline ISA only: sm_80-class) =================
__device__ __forceinline__ uint32_t smem_u32(const void* p) {
    uint32_t a;
    asm("{ .reg .u64 t; cvta.to.shared.u64 t, %1; cvt.u32.u64 %0, t; }"
        : "=r"(a) : "l"(p));
    return a;
}
__device__ __forceinline__ void cpasync16(uint32_t dst, const void* src) {
    asm volatile("cp.async.cg.shared.global [%0], [%1], 16;" :: "r"(dst), "l"(src));
}
__device__ __forceinline__ void cpasync_commit() {
    asm volatile("cp.async.commit_group;" ::: "memory");
}
template <int N>
__device__ __forceinline__ void cpasync_wait() {
    asm volatile("cp.async.wait_group %0;" :: "n"(N) : "memory");
}
__device__ __forceinline__ void ldsm4(uint32_t* r, uint32_t addr) {
    asm volatile("ldmatrix.sync.aligned.m8n8.x4.shared.b16 {%0,%1,%2,%3}, [%4];"
                 : "=r"(r[0]), "=r"(r[1]), "=r"(r[2]), "=r"(r[3]) : "r"(addr));
}
__device__ __forceinline__ void mma16816(float* c, const uint32_t* a,
                                         uint32_t b0, uint32_t b1) {
    asm volatile(
        "mma.sync.aligned.m16n8k16.row.col.f32.bf16.bf16.f32 "
        "{%0,%1,%2,%3}, {%4,%5,%6,%7}, {%8,%9}, {%0,%1,%2,%3};"
        : "+f"(c[0]), "+f"(c[1]), "+f"(c[2]), "+f"(c[3])
        : "r"(a[0]), "r"(a[1]), "r"(a[2]), "r"(a[3]), "r"(b0), "r"(b1));
}

// ================= three-term splits =================
union Pack24 {
    __nv_bfloat16 h[24];
    uint4 q[3];
};

__global__ __launch_bounds__(256) void split3_a(
    const float* __restrict__ src, __nv_bfloat16* __restrict__ dst, int n8)
{
    int i = blockIdx.x * 256 + threadIdx.x;
    if (i >= n8) return;
    float4 v0 = ((const float4*)src)[2 * i];
    float4 v1 = ((const float4*)src)[2 * i + 1];
    float f[8] = {v0.x, v0.y, v0.z, v0.w, v1.x, v1.y, v1.z, v1.w};
    Pack24 o;
#pragma unroll
    for (int j = 0; j < 8; j++) {
        __nv_bfloat16 hi = __float2bfloat16(f[j]);
        __nv_bfloat16 lo = __float2bfloat16(f[j] - __bfloat162float(hi));
        o.h[3 * j] = hi; o.h[3 * j + 1] = lo; o.h[3 * j + 2] = hi;
    }
    uint4* d = (uint4*)(dst + (size_t)24 * i);
    d[0] = o.q[0]; d[1] = o.q[1]; d[2] = o.q[2];
}

__global__ __launch_bounds__(256) void split3_w(
    const float* __restrict__ src, __nv_bfloat16* __restrict__ dst, int n8)
{
    int i = blockIdx.x * 256 + threadIdx.x;
    if (i >= n8) return;
    float4 v0 = ((const float4*)src)[2 * i];
    float4 v1 = ((const float4*)src)[2 * i + 1];
    float f[8] = {v0.x, v0.y, v0.z, v0.w, v1.x, v1.y, v1.z, v1.w};
    Pack24 o;
#pragma unroll
    for (int j = 0; j < 8; j++) {
        __nv_bfloat16 hi = __float2bfloat16(f[j]);
        __nv_bfloat16 lo = __float2bfloat16(f[j] - __bfloat162float(hi));
        o.h[3 * j] = hi; o.h[3 * j + 1] = hi; o.h[3 * j + 2] = lo;
    }
    uint4* d = (uint4*)(dst + (size_t)24 * i);
    d[0] = o.q[0]; d[1] = o.q[1]; d[2] = o.q[2];
}

// ================= bf16-split tensor-core GEMM (mma.sync, 128x128, 3-stage) =================
// C[m,n] = sum_k A'[m,k]*B'[n,k] (+bias[n]); A': M x KT bf16, B': Nw x KT bf16
#define KC 32                        // bf16 k per chunk
#define NCHUNK (KT / KC)             // 72
#define AST 40                       // padded smem row stride (bf16)
#define A_BYTES (128 * AST * 2)      // 10240 per stage
#define STAGE_BYTES (2 * A_BYTES)    // 20480 (A then B)
#define NSTAGE 3
#define GEMM_DSM (NSTAGE * STAGE_BYTES)   // 61440

__global__ __launch_bounds__(256, 2) void gemm_mma(
    const __nv_bfloat16* __restrict__ A, const __nv_bfloat16* __restrict__ Bw,
    const float* __restrict__ bias, float* __restrict__ C,
    int M, int Nw)
{
    extern __shared__ char dsm[];
    const uint32_t su = smem_u32(dsm);

    const int ntiles = Nw >> 7;
    const int m0 = (blockIdx.x / ntiles) << 7;
    const int n0 = (blockIdx.x % ntiles) << 7;
    const int tid = threadIdx.x;
    const int wid = tid >> 5, lane = tid & 31;
    const int wm = wid & 3, wn = wid >> 2;      // 4 x 2 warp grid; warp tile 32x64

    // ---- cp.async mapping: idx -> row = idx>>2 (0..127), 16B group = idx&3 ----
    const __nv_bfloat16* Ag[2];
    const __nv_bfloat16* Bg[2];
    uint32_t soA[2], soB[2];
#pragma unroll
    for (int i = 0; i < 2; i++) {
        int idx = tid + 256 * i;
        int row = idx >> 2, c = idx & 3;
        Ag[i] = A + (size_t)min(m0 + row, M - 1) * KT + c * 8;
        Bg[i] = Bw + (size_t)(n0 + row) * KT + c * 8;
        soA[i] = (uint32_t)(row * AST + c * 8) * 2;
        soB[i] = (uint32_t)A_BYTES + soA[i];
    }

    // prologue: stages 0..1
#pragma unroll
    for (int s = 0; s < NSTAGE - 1; s++) {
        uint32_t st = su + s * STAGE_BYTES;
        int ko = s * KC;
#pragma unroll
        for (int i = 0; i < 2; i++) {
            cpasync16(st + soA[i], Ag[i] + ko);
            cpasync16(st + soB[i], Bg[i] + ko);
        }
        cpasync_commit();
    }

    float acc[2][8][4];
#pragma unroll
    for (int mt = 0; mt < 2; mt++)
#pragma unroll
        for (int nt = 0; nt < 8; nt++)
#pragma unroll
            for (int q = 0; q < 4; q++) acc[mt][nt][q] = 0.f;

    const int lrow16 = lane & 15;
    const int lk8 = (lane >> 4) << 3;

    for (int c = 0; c < NCHUNK; c++) {
        cpasync_wait<NSTAGE - 2>();
        __syncthreads();
        // prefetch stage c+2 == stage (c-1)%3; all threads finished reading it
        // before the barrier above (it was chunk c-1's compute source).
        int pf = c + NSTAGE - 1;
        if (pf < NCHUNK) {
            uint32_t st = su + (pf % NSTAGE) * STAGE_BYTES;
            int ko = pf * KC;
#pragma unroll
            for (int i = 0; i < 2; i++) {
                cpasync16(st + soA[i], Ag[i] + ko);
                cpasync16(st + soB[i], Bg[i] + ko);
            }
        }
        cpasync_commit();

        const uint32_t sb = su + (c % NSTAGE) * STAGE_BYTES;
#pragma unroll
        for (int ks = 0; ks < 2; ks++) {
            uint32_t af[2][4];
#pragma unroll
            for (int mt = 0; mt < 2; mt++)
                ldsm4(af[mt], sb + (uint32_t)(((wm * 32 + mt * 16 + lrow16) * AST)
                                              + ks * 16 + lk8) * 2);
            uint32_t bf[4][4];
#pragma unroll
            for (int nt4 = 0; nt4 < 4; nt4++)
                ldsm4(bf[nt4], sb + A_BYTES
                      + (uint32_t)(((wn * 64 + nt4 * 16 + lrow16) * AST)
                                   + ks * 16 + lk8) * 2);
#pragma unroll
            for (int mt = 0; mt < 2; mt++)
#pragma unroll
                for (int nt4 = 0; nt4 < 4; nt4++) {
                    mma16816(acc[mt][nt4 * 2 + 0], af[mt], bf[nt4][0], bf[nt4][2]);
                    mma16816(acc[mt][nt4 * 2 + 1], af[mt], bf[nt4][1], bf[nt4][3]);
                }
        }
    }

    // ---- epilogue ----
#pragma unroll
    for (int mt = 0; mt < 2; mt++) {
        int r0 = m0 + wm * 32 + mt * 16 + (lane >> 2);
        int r1 = r0 + 8;
#pragma unroll
        for (int nt = 0; nt < 8; nt++) {
            int col = n0 + wn * 64 + nt * 8 + (lane & 3) * 2;
            float b0 = 0.f, b1 = 0.f;
            if (bias) { b0 = bias[col]; b1 = bias[col + 1]; }
            if (r0 < M) {
                float2 o; o.x = acc[mt][nt][0] + b0; o.y = acc[mt][nt][1] + b1;
                *(float2*)(C + (size_t)r0 * Nw + col) = o;
            }
            if (r1 < M) {
                float2 o; o.x = acc[mt][nt][2] + b0; o.y = acc[mt][nt][3] + b1;
                *(float2*)(C + (size_t)r1 * Nw + col) = o;
            }
        }
    }
}

// ---------------- agent pooling: 28x28 q image tokens -> 7x7 avg ----------------
__global__ __launch_bounds__(256) void pool_agent(float* __restrict__ agent)
{
    const int a = blockIdx.x;
    const int b = blockIdx.y;
    const int pr = a / 7, pc = a % 7;
    for (int c = threadIdx.x; c < CH; c += 256) {
        float s = 0.f;
#pragma unroll
        for (int i = 0; i < 4; i++)
#pragma unroll
            for (int j = 0; j < 4; j++) {
                int tok = 1 + (pr * 4 + i) * WIN + (pc * 4 + j);
                s += g_qkv[((size_t)(b * NTOK + tok)) * (3 * CH) + c];
            }
        agent[((size_t)b * AG + a) * CH + c] = s * (1.f / 16.f);
    }
}

// ---------------- jax bilinear (half-pixel upsample => clamped bilinear) ----------------
__device__ __forceinline__ float bilin7(const float* __restrict__ p, int r, int c)
{
    float fy = (r + 0.5f) * 0.25f - 0.5f;
    float fx = (c + 0.5f) * 0.25f - 0.5f;
    int y0 = (int)floorf(fy); float wy = fy - (float)y0;
    int x0 = (int)floorf(fx); float wx = fx - (float)x0;
    int y0c = min(max(y0, 0), 6), y1c = min(max(y0 + 1, 0), 6);
    int x0c = min(max(x0, 0), 6), x1c = min(max(x0 + 1, 0), 6);
    float v00 = p[y0c * 7 + x0c], v01 = p[y0c * 7 + x1c];
    float v10 = p[y1c * 7 + x0c], v11 = p[y1c * 7 + x1c];
    return (1.f - wy) * ((1.f - wx) * v00 + wx * v01)
         + wy * ((1.f - wx) * v10 + wx * v11);
}

__global__ __launch_bounds__(256) void build_pos1(
    const float* __restrict__ an, const float* __restrict__ ah,
    const float* __restrict__ aw, const float* __restrict__ ac)
{
    const int h = blockIdx.x / AG, a = blockIdx.x % AG;
    const float* anp = an + ((size_t)h * AG + a) * 49;
    float* out = g_pos1 + ((size_t)h * AG + a) * NTOK;
    if (threadIdx.x == 0) out[0] = ac[h * AG + a];
    for (int t = threadIdx.x; t < WIN * WIN; t += 256) {
        int r = t / WIN, c = t % WIN;
        out[1 + t] = bilin7(anp, r, c)
                   + ah[((size_t)h * AG + a) * WIN + r]
                   + aw[((size_t)h * AG + a) * WIN + c];
    }
}

__global__ __launch_bounds__(64) void build_pos2(
    const float* __restrict__ na, const float* __restrict__ ha,
    const float* __restrict__ wa, const float* __restrict__ ca)
{
    const int n = blockIdx.x;
    const int h = blockIdx.y;
    const int a = threadIdx.x;
    if (a >= AG) return;
    float v;
    if (n == 0) {
        v = ca[h * AG + a];
    } else {
        int t = n - 1, r = t / WIN, c = t % WIN;
        v = bilin7(na + ((size_t)h * AG + a) * 49, r, c)
          + ha[(size_t)h * WIN * AG + (size_t)r * AG + a]
          + wa[(size_t)h * WIN * AG + (size_t)c * AG + a];
    }
    g_pos2[((size_t)h * NTOK + n) * AG + a] = v;
}

// ---------------- stage 1: scores = scale*agent @ k^T + pos1 (raw) ----------------
__global__ __launch_bounds__(256) void s1_scores(const float* __restrict__ agent)
{
    const int b = blockIdx.x / NH, h = blockIdx.x % NH;
    __shared__ __align__(16) float agt[AG][HD];
    for (int i = threadIdx.x; i < AG * HD; i += 256) {
        int a = i / HD, d = i % HD;
        agt[a][d] = agent[((size_t)b * AG + a) * CH + h * HD + d] * SCALE;
    }
    __syncthreads();
    const float* pb = g_pos1 + (size_t)h * AG * NTOK;
    for (int n = threadIdx.x; n < NTOK; n += 256) {
        const float* kp = g_qkv + ((size_t)(b * NTOK + n)) * (3 * CH) + CH + h * HD;
        float kr[HD];
#pragma unroll
        for (int d = 0; d < HD; d += 4) {
            float4 t = *(const float4*)(kp + d);
            kr[d] = t.x; kr[d + 1] = t.y; kr[d + 2] = t.z; kr[d + 3] = t.w;
        }
        float* sout = g_s1 + ((size_t)(b * NH + h)) * AG * NTOK + n;
#pragma unroll 1
        for (int a = 0; a < AG; a++) {
            const float4* ap = (const float4*)agt[a];
            float acc = 0.f;
#pragma unroll
            for (int q = 0; q < HD / 4; q++) {
                float4 av = ap[q];
                acc += av.x * kr[4 * q] + av.y * kr[4 * q + 1]
                     + av.z * kr[4 * q + 2] + av.w * kr[4 * q + 3];
            }
            sout[(size_t)a * NTOK] = acc + pb[(size_t)a * NTOK + n];
        }
    }
}

// ---------------- stage 1: fused softmax + agent_v = softmax(scores) @ v ----------------
__global__ __launch_bounds__(256) void s1_av()
{
    const int b = blockIdx.x / NH, h = blockIdx.x % NH;
    __shared__ float sv[64][HD];
    __shared__ float sp[AG][64];
    __shared__ float smx[AG], sinv[AG];
    const int tid = threadIdx.x;
    const int wid = tid >> 5, lane = tid & 31;
    const int d  = tid & 63;
    const int a0 = tid >> 6;

    const size_t pbase = ((size_t)(b * NH + h)) * AG * NTOK;
    const float* S = g_s1 + pbase;

    // phase 1: per-agent max & sum (warp per agent)
    for (int a = wid; a < AG; a += 8) {
        const float* row = S + (size_t)a * NTOK;
        float mx = -1e30f;
        for (int n = lane; n < NTOK; n += 32) mx = fmaxf(mx, row[n]);
#pragma unroll
        for (int o = 16; o > 0; o >>= 1)
            mx = fmaxf(mx, __shfl_xor_sync(0xFFFFFFFFu, mx, o));
        float sm = 0.f;
        for (int n = lane; n < NTOK; n += 32) sm += expf(row[n] - mx);
#pragma unroll
        for (int o = 16; o > 0; o >>= 1)
            sm += __shfl_xor_sync(0xFFFFFFFFu, sm, o);
        if (lane == 0) { smx[a] = mx; sinv[a] = 1.f / sm; }
    }
    __syncthreads();

    float acc[13];
#pragma unroll
    for (int i = 0; i < 13; i++) acc[i] = 0.f;

    for (int n0 = 0; n0 < NTOK; n0 += 64) {
        int nt = min(64, NTOK - n0);
        __syncthreads();
        for (int i = tid; i < nt * HD; i += 256) {
            int nn = i >> 6, dd = i & 63;
            sv[nn][dd] = g_qkv[((size_t)(b * NTOK + n0 + nn)) * (3 * CH) + 2 * CH + h * HD + dd];
        }
        for (int i = tid; i < AG * 64; i += 256) {
            int a = i >> 6, nn = i & 63;
            if (nn < nt)
                sp[a][nn] = expf(S[(size_t)a * NTOK + n0 + nn] - smx[a]);
        }
        __syncthreads();
        for (int nn = 0; nn < nt; nn++) {
            float vv = sv[nn][d];
#pragma unroll
            for (int i = 0; i < 13; i++) {
                int a = a0 + 4 * i;
                if (a < AG) acc[i] += sp[a][nn] * vv;
            }
        }
    }
#pragma unroll
    for (int i = 0; i < 13; i++) {
        int a = a0 + 4 * i;
        if (a < AG)
            g_agentv[((size_t)(b * NH + h) * AG + a) * HD + d] = acc[i] * sinv[a];
    }
}

// ---------------- stage 2 fused ----------------
__global__ __launch_bounds__(256) void stage2(const float* __restrict__ agent)
{
    const int h = blockIdx.y, b = blockIdx.z;
    __shared__ __align__(16) float agt[AG][HD];
    __shared__ __align__(16) float sv[AG][HD];
    for (int i = threadIdx.x; i < AG * HD; i += 256) {
        int a = i / HD, d = i % HD;
        agt[a][d] = agent[((size_t)b * AG + a) * CH + h * HD + d] * SCALE;
        sv[a][d]  = g_agentv[((size_t)(b * NH + h) * AG + a) * HD + d];
    }
    __syncthreads();

    const int n = blockIdx.x * 256 + threadIdx.x;
    if (n >= NTOK) return;

    float qr[HD];
    const float* qp = g_qkv + ((size_t)(b * NTOK + n)) * (3 * CH) + h * HD;
#pragma unroll
    for (int dd = 0; dd < HD; dd += 4) {
        float4 t = *(const float4*)(qp + dd);
        qr[dd] = t.x; qr[dd + 1] = t.y; qr[dd + 2] = t.z; qr[dd + 3] = t.w;
    }

    const float* pb = g_pos2 + ((size_t)h * NTOK + n) * AG;
    float sc[AG];
    float mx = -1e30f;
#pragma unroll 1
    for (int a = 0; a < AG; a++) {
        const float4* ap = (const float4*)agt[a];
        float acc = 0.f;
#pragma unroll
        for (int q = 0; q < HD / 4; q++) {
            float4 av = ap[q];
            acc += av.x * qr[4 * q] + av.y * qr[4 * q + 1]
                 + av.z * qr[4 * q + 2] + av.w * qr[4 * q + 3];
        }
        sc[a] = acc + pb[a];
        mx = fmaxf(mx, sc[a]);
    }
    float sum = 0.f;
#pragma unroll
    for (int a = 0; a < AG; a++) {
        float e = expf(sc[a] - mx);
        sc[a] = e; sum += e;
    }
    float inv = 1.f / sum;
#pragma unroll
    for (int a = 0; a < AG; a++) sc[a] *= inv;

    float od[HD];
#pragma unroll
    for (int dd = 0; dd < HD; dd++) od[dd] = 0.f;
#pragma unroll 1
    for (int a = 0; a < AG; a++) {
        float w = sc[a];
        const float4* vp = (const float4*)sv[a];
#pragma unroll
        for (int q = 0; q < HD / 4; q++) {
            float4 t = vp[q];
            od[4 * q]     += w * t.x; od[4 * q + 1] += w * t.y;
            od[4 * q + 2] += w * t.z; od[4 * q + 3] += w * t.w;
        }
    }
    float* op = g_attn + ((size_t)(b * NTOK + n)) * CH + h * HD;
#pragma unroll
    for (int dd = 0; dd < HD; dd += 4) {
        float4 t;
        t.x = od[dd]; t.y = od[dd + 1]; t.z = od[dd + 2]; t.w = od[dd + 3];
        *(float4*)(op + dd) = t;
    }
}

// ---------------- depthwise 3x3 conv on v image tokens ----------------
__global__ __launch_bounds__(256) void dwc_add(
    const float* __restrict__ w, const float* __restrict__ bias)
{
    const int t = blockIdx.x;
    const int b = blockIdx.y;
    const int r = t / WIN, cc = t % WIN;
    for (int c = threadIdx.x; c < CH; c += 256) {
        float acc = bias[c];
#pragma unroll
        for (int ky = 0; ky < 3; ky++) {
            int rr = r + ky - 1;
            if (rr < 0 || rr >= WIN) continue;
#pragma unroll
            for (int kx = 0; kx < 3; kx++) {
                int c2 = cc + kx - 1;
                if (c2 < 0 || c2 >= WIN) continue;
                acc += w[(ky * 3 + kx) * CH + c]
                     * g_qkv[((size_t)(b * NTOK + 1 + rr * WIN + c2)) * (3 * CH) + 2 * CH + c];
            }
        }
        g_attn[((size_t)(b * NTOK + 1 + t)) * CH + c] += acc;
    }
}

// ---------------- launch ----------------
extern "C" void kernel_launch(void* const* d_in, const int* in_sizes, int n_in,
                              void* d_out, int out_size)
{
    const float* x      = (const float*)d_in[0];
    const float* w_qkv  = (const float*)d_in[1];
    const float* w_proj = (const float*)d_in[2];
    const float* b_proj = (const float*)d_in[3];
    const float* dwc_w  = (const float*)d_in[4];
    const float* dwc_b  = (const float*)d_in[5];
    const float* an_b   = (const float*)d_in[6];
    const float* ah_b   = (const float*)d_in[7];
    const float* aw_b   = (const float*)d_in[8];
    const float* na_b   = (const float*)d_in[9];
    const float* ha_b   = (const float*)d_in[10];
    const float* wa_b   = (const float*)d_in[11];
    const float* ac_b   = (const float*)d_in[12];
    const float* ca_b   = (const float*)d_in[13];
    float* out = (float*)d_out;

    float *p_qkv, *p_agent, *p_attn;
    cudaGetSymbolAddress((void**)&p_qkv, g_qkv);
    cudaGetSymbolAddress((void**)&p_agent, g_agent);
    cudaGetSymbolAddress((void**)&p_attn, g_attn);
    __nv_bfloat16 *p_xs, *p_as, *p_wqs, *p_wps;
    cudaGetSymbolAddress((void**)&p_xs, g_xs);
    cudaGetSymbolAddress((void**)&p_as, g_as);
    cudaGetSymbolAddress((void**)&p_wqs, g_wqs);
    cudaGetSymbolAddress((void**)&p_wps, g_wps);

    cudaFuncSetAttribute(gemm_mma, cudaFuncAttributeMaxDynamicSharedMemorySize,
                         GEMM_DSM);

    const int M = BATCH * NTOK;              // 50240
    const int MTILES = (M + 127) / 128;      // 393

    // 0) three-term bf16 splits of x and weights
    const int x8 = M * CH / 8;
    split3_a<<<(x8 + 255) / 256, 256>>>(x, p_xs, x8);
    const int wq8 = 3 * CH * CH / 8;
    split3_w<<<(wq8 + 255) / 256, 256>>>(w_qkv, p_wqs, wq8);
    const int wp8 = CH * CH / 8;
    split3_w<<<(wp8 + 255) / 256, 256>>>(w_proj, p_wps, wp8);

    // 1) QKV GEMM on tensor cores (mma.sync, 128x128 tiles, 3-stage, 1 barrier)
    gemm_mma<<<MTILES * (3 * CH / 128), 256, GEMM_DSM>>>(
        p_xs, p_wqs, nullptr, p_qkv, M, 3 * CH);

    // 2) agent pooling
    pool_agent<<<dim3(AG, BATCH), 256>>>(p_agent);

    // 3/4) position biases
    build_pos1<<<NH * AG, 256>>>(an_b, ah_b, aw_b, ac_b);
    build_pos2<<<dim3(NTOK, NH), 64>>>(na_b, ha_b, wa_b, ca_b);

    // 5) stage-1 scores, fused softmax+AV
    s1_scores<<<BATCH * NH, 256>>>(p_agent);
    s1_av<<<BATCH * NH, 256>>>();

    // 6) stage-2 fused attention
    stage2<<<dim3((NTOK + 255) / 256, NH, BATCH), 256>>>(p_agent);

    // 7) depthwise conv add
    dwc_add<<<dim3(WIN * WIN, BATCH), 256>>>(dwc_w, dwc_b);

    // 8) output projection on tensor cores (split attn first)
    split3_a<<<(x8 + 255) / 256, 256>>>(p_attn, p_as, x8);
    gemm_mma<<<MTILES * (CH / 128), 256, GEMM_DSM>>>(
        p_as, p_wps, b_proj, out, M, CH);
}

// round 13
// speedup vs baseline: 1.1597x; 1.0695x over previous
#include <cuda_runtime.h>
#include <cuda_bf16.h>
#include <math.h>
#include <stdint.h>

// ---------------- problem constants ----------------
#define BATCH 64
#define NTOK  785          // 1 + 28*28
#define CH    768
#define NH    12
#define HD    64
#define AG    49
#define WIN   28
#define SCALE 0.125f       // hd^-0.5

// ---------------- scratch (device globals; no allocs allowed) ----------------
__device__ __align__(16) float g_qkv[(size_t)BATCH * NTOK * 3 * CH];   // (B,N,3C)
__device__ __align__(16) float g_agent[(size_t)BATCH * AG * CH];       // (B,A,C)
__device__ __align__(16) float g_agentv[(size_t)BATCH * NH * AG * HD]; // (B,H,A,hd)
__device__ __align__(16) float g_attn[(size_t)BATCH * NTOK * CH];      // stage2 output
__device__ __align__(16) float g_pos1[(size_t)NH * AG * NTOK];         // (H,A,N)
__device__ __align__(16) float g_pos2[(size_t)NH * NTOK * AG];         // (H,N,A)
__device__ __align__(16) float g_s1[(size_t)BATCH * NH * AG * NTOK];   // stage-1 raw scores

// bf16 three-term split buffers (K tripled: 768 -> 2304)
// per original k: A' = {hi_a, lo_a, hi_a},  W' = {hi_w, hi_w, lo_w}
// => dot = hi*hi + lo_a*hi_w + hi_a*lo_w  (drops only lo*lo ~ 2^-18)
#define KT 2304
__device__ __align__(16) __nv_bfloat16 g_xs[(size_t)BATCH * NTOK * KT];   // x split (A pattern)
__device__ __align__(16) __nv_bfloat16 g_as[(size_t)BATCH * NTOK * KT];   // attn+dwc split (A pattern)
__device__ __align__(16) __nv_bfloat16 g_wqs[(size_t)(3 * CH) * KT];      // w_qkv split (W pattern)
__device__ __align__(16) __nv_bfloat16 g_wps[(size_t)CH * KT];            // w_proj split (W pattern)

// ================= PTX helpers (baseline ISA only: sm_80-class) =================
__device__ __forceinline__ uint32_t smem_u32(const void* p) {
    uint32_t a;
    asm("{ .reg .u64 t; cvta.to.shared.u64 t, %1; cvt.u32.u64 %0, t; }"
        : "=r"(a) : "l"(p));
    return a;
}
__device__ __forceinline__ void cpasync16(uint32_t dst, const void* src) {
    asm volatile("cp.async.cg.shared.global [%0], [%1], 16;" :: "r"(dst), "l"(src));
}
__device__ __forceinline__ void cpasync_commit() {
    asm volatile("cp.async.commit_group;" ::: "memory");
}
template <int N>
__device__ __forceinline__ void cpasync_wait() {
    asm volatile("cp.async.wait_group %0;" :: "n"(N) : "memory");
}
__device__ __forceinline__ void ldsm4(uint32_t* r, uint32_t addr) {
    asm volatile("ldmatrix.sync.aligned.m8n8.x4.shared.b16 {%0,%1,%2,%3}, [%4];"
                 : "=r"(r[0]), "=r"(r[1]), "=r"(r[2]), "=r"(r[3]) : "r"(addr));
}
__device__ __forceinline__ void mma16816(float* c, const uint32_t* a,
                                         uint32_t b0, uint32_t b1) {
    asm volatile(
        "mma.sync.aligned.m16n8k16.row.col.f32.bf16.bf16.f32 "
        "{%0,%1,%2,%3}, {%4,%5,%6,%7}, {%8,%9}, {%0,%1,%2,%3};"
        : "+f"(c[0]), "+f"(c[1]), "+f"(c[2]), "+f"(c[3])
        : "r"(a[0]), "r"(a[1]), "r"(a[2]), "r"(a[3]), "r"(b0), "r"(b1));
}

// ================= three-term splits =================
union Pack24 {
    __nv_bfloat16 h[24];
    uint4 q[3];
};

__global__ __launch_bounds__(256) void split3_a(
    const float* __restrict__ src, __nv_bfloat16* __restrict__ dst, int n8)
{
    int i = blockIdx.x * 256 + threadIdx.x;
    if (i >= n8) return;
    float4 v0 = ((const float4*)src)[2 * i];
    float4 v1 = ((const float4*)src)[2 * i + 1];
    float f[8] = {v0.x, v0.y, v0.z, v0.w, v1.x, v1.y, v1.z, v1.w};
    Pack24 o;
#pragma unroll
    for (int j = 0; j < 8; j++) {
        __nv_bfloat16 hi = __float2bfloat16(f[j]);
        __nv_bfloat16 lo = __float2bfloat16(f[j] - __bfloat162float(hi));
        o.h[3 * j] = hi; o.h[3 * j + 1] = lo; o.h[3 * j + 2] = hi;
    }
    uint4* d = (uint4*)(dst + (size_t)24 * i);
    d[0] = o.q[0]; d[1] = o.q[1]; d[2] = o.q[2];
}

__global__ __launch_bounds__(256) void split3_w(
    const float* __restrict__ src, __nv_bfloat16* __restrict__ dst, int n8)
{
    int i = blockIdx.x * 256 + threadIdx.x;
    if (i >= n8) return;
    float4 v0 = ((const float4*)src)[2 * i];
    float4 v1 = ((const float4*)src)[2 * i + 1];
    float f[8] = {v0.x, v0.y, v0.z, v0.w, v1.x, v1.y, v1.z, v1.w};
    Pack24 o;
#pragma unroll
    for (int j = 0; j < 8; j++) {
        __nv_bfloat16 hi = __float2bfloat16(f[j]);
        __nv_bfloat16 lo = __float2bfloat16(f[j] - __bfloat162float(hi));
        o.h[3 * j] = hi; o.h[3 * j + 1] = hi; o.h[3 * j + 2] = lo;
    }
    uint4* d = (uint4*)(dst + (size_t)24 * i);
    d[0] = o.q[0]; d[1] = o.q[1]; d[2] = o.q[2];
}

// ================= bf16-split tensor-core GEMM (mma.sync, 128x128, 4-stage) =================
// C[m,n] = sum_k A'[m,k]*B'[n,k] (+bias[n]); A': M x KT bf16, B': Nw x KT bf16
#define KC 32                        // bf16 k per chunk
#define NCHUNK (KT / KC)             // 72
#define AST 40                       // padded smem row stride (bf16)
#define A_BYTES (128 * AST * 2)      // 10240 per stage
#define STAGE_BYTES (2 * A_BYTES)    // 20480 (A then B)
#define NSTAGE 4
#define GEMM_DSM (NSTAGE * STAGE_BYTES)   // 81920

__global__ __launch_bounds__(256, 2) void gemm_mma(
    const __nv_bfloat16* __restrict__ A, const __nv_bfloat16* __restrict__ Bw,
    const float* __restrict__ bias, float* __restrict__ C,
    int M, int Nw)
{
    extern __shared__ char dsm[];
    const uint32_t su = smem_u32(dsm);

    const int ntiles = Nw >> 7;
    const int m0 = (blockIdx.x / ntiles) << 7;
    const int n0 = (blockIdx.x % ntiles) << 7;
    const int tid = threadIdx.x;
    const int wid = tid >> 5, lane = tid & 31;
    const int wm = wid & 3, wn = wid >> 2;      // 4 x 2 warp grid; warp tile 32x64

    // ---- cp.async mapping: idx -> row = idx>>2 (0..127), 16B group = idx&3 ----
    // dst offsets include su, so per-stage dst = reg + compile-time immediate
    const __nv_bfloat16* Ag[2];
    const __nv_bfloat16* Bg[2];
    uint32_t dA[2], dB[2];
#pragma unroll
    for (int i = 0; i < 2; i++) {
        int idx = tid + 256 * i;
        int row = idx >> 2, c = idx & 3;
        Ag[i] = A + (size_t)min(m0 + row, M - 1) * KT + c * 8;
        Bg[i] = Bw + (size_t)(n0 + row) * KT + c * 8;
        dA[i] = su + (uint32_t)(row * AST + c * 8) * 2;
        dB[i] = dA[i] + (uint32_t)A_BYTES;
    }

    // ---- ldmatrix addresses (include su): addr = reg + stage-immediate ----
    const int lrow16 = lane & 15;
    const int lk8 = (lane >> 4) << 3;
    uint32_t lA[2][2], lB[2][4];     // [ks][mt] / [ks][nt4]
#pragma unroll
    for (int ks = 0; ks < 2; ks++) {
#pragma unroll
        for (int mt = 0; mt < 2; mt++)
            lA[ks][mt] = su + (uint32_t)(((wm * 32 + mt * 16 + lrow16) * AST)
                                         + ks * 16 + lk8) * 2;
#pragma unroll
        for (int nt4 = 0; nt4 < 4; nt4++)
            lB[ks][nt4] = su + (uint32_t)A_BYTES
                        + (uint32_t)(((wn * 64 + nt4 * 16 + lrow16) * AST)
                                     + ks * 16 + lk8) * 2;
    }

    // prologue: stages 0..2
#pragma unroll
    for (int s = 0; s < NSTAGE - 1; s++) {
        int ko = s * KC;
#pragma unroll
        for (int i = 0; i < 2; i++) {
            cpasync16(dA[i] + s * STAGE_BYTES, Ag[i] + ko);
            cpasync16(dB[i] + s * STAGE_BYTES, Bg[i] + ko);
        }
        cpasync_commit();
    }

    float acc[2][8][4];
#pragma unroll
    for (int mt = 0; mt < 2; mt++)
#pragma unroll
        for (int nt = 0; nt < 8; nt++)
#pragma unroll
            for (int q = 0; q < 4; q++) acc[mt][nt][q] = 0.f;

    for (int c0 = 0; c0 < NCHUNK; c0 += NSTAGE) {
#pragma unroll
        for (int s = 0; s < NSTAGE; s++) {
            const int c = c0 + s;
            cpasync_wait<NSTAGE - 2>();
            __syncthreads();
            // prefetch into stage (s+3)%4 (compile-time) = chunk c-1's stage;
            // all threads finished reading it before the barrier above.
            const int pf = c + NSTAGE - 1;
            const uint32_t pso = ((s + NSTAGE - 1) % NSTAGE) * STAGE_BYTES;
            if (pf < NCHUNK) {
                int ko = pf * KC;
#pragma unroll
                for (int i = 0; i < 2; i++) {
                    cpasync16(dA[i] + pso, Ag[i] + ko);
                    cpasync16(dB[i] + pso, Bg[i] + ko);
                }
            }
            cpasync_commit();

            const uint32_t so = s * STAGE_BYTES;    // compile-time
#pragma unroll
            for (int ks = 0; ks < 2; ks++) {
                uint32_t af[2][4];
#pragma unroll
                for (int mt = 0; mt < 2; mt++)
                    ldsm4(af[mt], lA[ks][mt] + so);
                uint32_t bf[4][4];
#pragma unroll
                for (int nt4 = 0; nt4 < 4; nt4++)
                    ldsm4(bf[nt4], lB[ks][nt4] + so);
#pragma unroll
                for (int mt = 0; mt < 2; mt++)
#pragma unroll
                    for (int nt4 = 0; nt4 < 4; nt4++) {
                        mma16816(acc[mt][nt4 * 2 + 0], af[mt], bf[nt4][0], bf[nt4][2]);
                        mma16816(acc[mt][nt4 * 2 + 1], af[mt], bf[nt4][1], bf[nt4][3]);
                    }
            }
        }
    }

    // ---- epilogue ----
#pragma unroll
    for (int mt = 0; mt < 2; mt++) {
        int r0 = m0 + wm * 32 + mt * 16 + (lane >> 2);
        int r1 = r0 + 8;
#pragma unroll
        for (int nt = 0; nt < 8; nt++) {
            int col = n0 + wn * 64 + nt * 8 + (lane & 3) * 2;
            float b0 = 0.f, b1 = 0.f;
            if (bias) { b0 = bias[col]; b1 = bias[col + 1]; }
            if (r0 < M) {
                float2 o; o.x = acc[mt][nt][0] + b0; o.y = acc[mt][nt][1] + b1;
                *(float2*)(C + (size_t)r0 * Nw + col) = o;
            }
            if (r1 < M) {
                float2 o; o.x = acc[mt][nt][2] + b0; o.y = acc[mt][nt][3] + b1;
                *(float2*)(C + (size_t)r1 * Nw + col) = o;
            }
        }
    }
}

// ---------------- agent pooling: 28x28 q image tokens -> 7x7 avg ----------------
__global__ __launch_bounds__(256) void pool_agent(float* __restrict__ agent)
{
    const int a = blockIdx.x;
    const int b = blockIdx.y;
    const int pr = a / 7, pc = a % 7;
    for (int c = threadIdx.x; c < CH; c += 256) {
        float s = 0.f;
#pragma unroll
        for (int i = 0; i < 4; i++)
#pragma unroll
            for (int j = 0; j < 4; j++) {
                int tok = 1 + (pr * 4 + i) * WIN + (pc * 4 + j);
                s += g_qkv[((size_t)(b * NTOK + tok)) * (3 * CH) + c];
            }
        agent[((size_t)b * AG + a) * CH + c] = s * (1.f / 16.f);
    }
}

// ---------------- jax bilinear (half-pixel upsample => clamped bilinear) ----------------
__device__ __forceinline__ float bilin7(const float* __restrict__ p, int r, int c)
{
    float fy = (r + 0.5f) * 0.25f - 0.5f;
    float fx = (c + 0.5f) * 0.25f - 0.5f;
    int y0 = (int)floorf(fy); float wy = fy - (float)y0;
    int x0 = (int)floorf(fx); float wx = fx - (float)x0;
    int y0c = min(max(y0, 0), 6), y1c = min(max(y0 + 1, 0), 6);
    int x0c = min(max(x0, 0), 6), x1c = min(max(x0 + 1, 0), 6);
    float v00 = p[y0c * 7 + x0c], v01 = p[y0c * 7 + x1c];
    float v10 = p[y1c * 7 + x0c], v11 = p[y1c * 7 + x1c];
    return (1.f - wy) * ((1.f - wx) * v00 + wx * v01)
         + wy * ((1.f - wx) * v10 + wx * v11);
}

__global__ __launch_bounds__(256) void build_pos1(
    const float* __restrict__ an, const float* __restrict__ ah,
    const float* __restrict__ aw, const float* __restrict__ ac)
{
    const int h = blockIdx.x / AG, a = blockIdx.x % AG;
    const float* anp = an + ((size_t)h * AG + a) * 49;
    float* out = g_pos1 + ((size_t)h * AG + a) * NTOK;
    if (threadIdx.x == 0) out[0] = ac[h * AG + a];
    for (int t = threadIdx.x; t < WIN * WIN; t += 256) {
        int r = t / WIN, c = t % WIN;
        out[1 + t] = bilin7(anp, r, c)
                   + ah[((size_t)h * AG + a) * WIN + r]
                   + aw[((size_t)h * AG + a) * WIN + c];
    }
}

__global__ __launch_bounds__(64) void build_pos2(
    const float* __restrict__ na, const float* __restrict__ ha,
    const float* __restrict__ wa, const float* __restrict__ ca)
{
    const int n = blockIdx.x;
    const int h = blockIdx.y;
    const int a = threadIdx.x;
    if (a >= AG) return;
    float v;
    if (n == 0) {
        v = ca[h * AG + a];
    } else {
        int t = n - 1, r = t / WIN, c = t % WIN;
        v = bilin7(na + ((size_t)h * AG + a) * 49, r, c)
          + ha[(size_t)h * WIN * AG + (size_t)r * AG + a]
          + wa[(size_t)h * WIN * AG + (size_t)c * AG + a];
    }
    g_pos2[((size_t)h * NTOK + n) * AG + a] = v;
}

// ---------------- stage 1: scores = scale*agent @ k^T + pos1 (raw) ----------------
__global__ __launch_bounds__(256) void s1_scores(const float* __restrict__ agent)
{
    const int b = blockIdx.x / NH, h = blockIdx.x % NH;
    __shared__ __align__(16) float agt[AG][HD];
    for (int i = threadIdx.x; i < AG * HD; i += 256) {
        int a = i / HD, d = i % HD;
        agt[a][d] = agent[((size_t)b * AG + a) * CH + h * HD + d] * SCALE;
    }
    __syncthreads();
    const float* pb = g_pos1 + (size_t)h * AG * NTOK;
    for (int n = threadIdx.x; n < NTOK; n += 256) {
        const float* kp = g_qkv + ((size_t)(b * NTOK + n)) * (3 * CH) + CH + h * HD;
        float kr[HD];
#pragma unroll
        for (int d = 0; d < HD; d += 4) {
            float4 t = *(const float4*)(kp + d);
            kr[d] = t.x; kr[d + 1] = t.y; kr[d + 2] = t.z; kr[d + 3] = t.w;
        }
        float* sout = g_s1 + ((size_t)(b * NH + h)) * AG * NTOK + n;
#pragma unroll 1
        for (int a = 0; a < AG; a++) {
            const float4* ap = (const float4*)agt[a];
            float acc = 0.f;
#pragma unroll
            for (int q = 0; q < HD / 4; q++) {
                float4 av = ap[q];
                acc += av.x * kr[4 * q] + av.y * kr[4 * q + 1]
                     + av.z * kr[4 * q + 2] + av.w * kr[4 * q + 3];
            }
            sout[(size_t)a * NTOK] = acc + pb[(size_t)a * NTOK + n];
        }
    }
}

// ---------------- stage 1: fused softmax + agent_v = softmax(scores) @ v ----------------
__global__ __launch_bounds__(256) void s1_av()
{
    const int b = blockIdx.x / NH, h = blockIdx.x % NH;
    __shared__ float sv[64][HD];
    __shared__ float sp[AG][64];
    __shared__ float smx[AG], sinv[AG];
    const int tid = threadIdx.x;
    const int wid = tid >> 5, lane = tid & 31;
    const int d  = tid & 63;
    const int a0 = tid >> 6;

    const size_t pbase = ((size_t)(b * NH + h)) * AG * NTOK;
    const float* S = g_s1 + pbase;

    // phase 1: per-agent max & sum (warp per agent)
    for (int a = wid; a < AG; a += 8) {
        const float* row = S + (size_t)a * NTOK;
        float mx = -1e30f;
        for (int n = lane; n < NTOK; n += 32) mx = fmaxf(mx, row[n]);
#pragma unroll
        for (int o = 16; o > 0; o >>= 1)
            mx = fmaxf(mx, __shfl_xor_sync(0xFFFFFFFFu, mx, o));
        float sm = 0.f;
        for (int n = lane; n < NTOK; n += 32) sm += expf(row[n] - mx);
#pragma unroll
        for (int o = 16; o > 0; o >>= 1)
            sm += __shfl_xor_sync(0xFFFFFFFFu, sm, o);
        if (lane == 0) { smx[a] = mx; sinv[a] = 1.f / sm; }
    }
    __syncthreads();

    float acc[13];
#pragma unroll
    for (int i = 0; i < 13; i++) acc[i] = 0.f;

    for (int n0 = 0; n0 < NTOK; n0 += 64) {
        int nt = min(64, NTOK - n0);
        __syncthreads();
        for (int i = tid; i < nt * HD; i += 256) {
            int nn = i >> 6, dd = i & 63;
            sv[nn][dd] = g_qkv[((size_t)(b * NTOK + n0 + nn)) * (3 * CH) + 2 * CH + h * HD + dd];
        }
        for (int i = tid; i < AG * 64; i += 256) {
            int a = i >> 6, nn = i & 63;
            if (nn < nt)
                sp[a][nn] = expf(S[(size_t)a * NTOK + n0 + nn] - smx[a]);
        }
        __syncthreads();
        for (int nn = 0; nn < nt; nn++) {
            float vv = sv[nn][d];
#pragma unroll
            for (int i = 0; i < 13; i++) {
                int a = a0 + 4 * i;
                if (a < AG) acc[i] += sp[a][nn] * vv;
            }
        }
    }
#pragma unroll
    for (int i = 0; i < 13; i++) {
        int a = a0 + 4 * i;
        if (a < AG)
            g_agentv[((size_t)(b * NH + h) * AG + a) * HD + d] = acc[i] * sinv[a];
    }
}

// ---------------- stage 2 fused ----------------
__global__ __launch_bounds__(256) void stage2(const float* __restrict__ agent)
{
    const int h = blockIdx.y, b = blockIdx.z;
    __shared__ __align__(16) float agt[AG][HD];
    __shared__ __align__(16) float sv[AG][HD];
    for (int i = threadIdx.x; i < AG * HD; i += 256) {
        int a = i / HD, d = i % HD;
        agt[a][d] = agent[((size_t)b * AG + a) * CH + h * HD + d] * SCALE;
        sv[a][d]  = g_agentv[((size_t)(b * NH + h) * AG + a) * HD + d];
    }
    __syncthreads();

    const int n = blockIdx.x * 256 + threadIdx.x;
    if (n >= NTOK) return;

    float qr[HD];
    const float* qp = g_qkv + ((size_t)(b * NTOK + n)) * (3 * CH) + h * HD;
#pragma unroll
    for (int dd = 0; dd < HD; dd += 4) {
        float4 t = *(const float4*)(qp + dd);
        qr[dd] = t.x; qr[dd + 1] = t.y; qr[dd + 2] = t.z; qr[dd + 3] = t.w;
    }

    const float* pb = g_pos2 + ((size_t)h * NTOK + n) * AG;
    float sc[AG];
    float mx = -1e30f;
#pragma unroll 1
    for (int a = 0; a < AG; a++) {
        const float4* ap = (const float4*)agt[a];
        float acc = 0.f;
#pragma unroll
        for (int q = 0; q < HD / 4; q++) {
            float4 av = ap[q];
            acc += av.x * qr[4 * q] + av.y * qr[4 * q + 1]
                 + av.z * qr[4 * q + 2] + av.w * qr[4 * q + 3];
        }
        sc[a] = acc + pb[a];
        mx = fmaxf(mx, sc[a]);
    }
    float sum = 0.f;
#pragma unroll
    for (int a = 0; a < AG; a++) {
        float e = expf(sc[a] - mx);
        sc[a] = e; sum += e;
    }
    float inv = 1.f / sum;
#pragma unroll
    for (int a = 0; a < AG; a++) sc[a] *= inv;

    float od[HD];
#pragma unroll
    for (int dd = 0; dd < HD; dd++) od[dd] = 0.f;
#pragma unroll 1
    for (int a = 0; a < AG; a++) {
        float w = sc[a];
        const float4* vp = (const float4*)sv[a];
#pragma unroll
        for (int q = 0; q < HD / 4; q++) {
            float4 t = vp[q];
            od[4 * q]     += w * t.x; od[4 * q + 1] += w * t.y;
            od[4 * q + 2] += w * t.z; od[4 * q + 3] += w * t.w;
        }
    }
    float* op = g_attn + ((size_t)(b * NTOK + n)) * CH + h * HD;
#pragma unroll
    for (int dd = 0; dd < HD; dd += 4) {
        float4 t;
        t.x = od[dd]; t.y = od[dd + 1]; t.z = od[dd + 2]; t.w = od[dd + 3];
        *(float4*)(op + dd) = t;
    }
}

// ---------------- fused: depthwise conv add + three-term split into g_as ----------------
// token 0: split(stage2 out). tokens >=1: split(stage2 out + conv + bias).
__global__ __launch_bounds__(256) void dwc_split(
    const float* __restrict__ w, const float* __restrict__ bias)
{
    const int t = blockIdx.x;          // 0..784 token index
    const int b = blockIdx.y;
    const float* src = g_attn + ((size_t)(b * NTOK + t)) * CH;
    __nv_bfloat16* dst = g_as + ((size_t)(b * NTOK + t)) * KT;

    if (t == 0) {
        for (int c = threadIdx.x; c < CH; c += 256) {
            float v = src[c];
            __nv_bfloat16 hi = __float2bfloat16(v);
            __nv_bfloat16 lo = __float2bfloat16(v - __bfloat162float(hi));
            dst[3 * c] = hi; dst[3 * c + 1] = lo; dst[3 * c + 2] = hi;
        }
        return;
    }
    const int ti = t - 1;
    const int r = ti / WIN, cc = ti % WIN;
    for (int c = threadIdx.x; c < CH; c += 256) {
        float acc = bias[c] + src[c];
#pragma unroll
        for (int ky = 0; ky < 3; ky++) {
            int rr = r + ky - 1;
            if (rr < 0 || rr >= WIN) continue;
#pragma unroll
            for (int kx = 0; kx < 3; kx++) {
                int c2 = cc + kx - 1;
                if (c2 < 0 || c2 >= WIN) continue;
                acc += w[(ky * 3 + kx) * CH + c]
                     * g_qkv[((size_t)(b * NTOK + 1 + rr * WIN + c2)) * (3 * CH) + 2 * CH + c];
            }
        }
        __nv_bfloat16 hi = __float2bfloat16(acc);
        __nv_bfloat16 lo = __float2bfloat16(acc - __bfloat162float(hi));
        dst[3 * c] = hi; dst[3 * c + 1] = lo; dst[3 * c + 2] = hi;
    }
}

// ---------------- launch ----------------
extern "C" void kernel_launch(void* const* d_in, const int* in_sizes, int n_in,
                              void* d_out, int out_size)
{
    const float* x      = (const float*)d_in[0];
    const float* w_qkv  = (const float*)d_in[1];
    const float* w_proj = (const float*)d_in[2];
    const float* b_proj = (const float*)d_in[3];
    const float* dwc_w  = (const float*)d_in[4];
    const float* dwc_b  = (const float*)d_in[5];
    const float* an_b   = (const float*)d_in[6];
    const float* ah_b   = (const float*)d_in[7];
    const float* aw_b   = (const float*)d_in[8];
    const float* na_b   = (const float*)d_in[9];
    const float* ha_b   = (const float*)d_in[10];
    const float* wa_b   = (const float*)d_in[11];
    const float* ac_b   = (const float*)d_in[12];
    const float* ca_b   = (const float*)d_in[13];
    float* out = (float*)d_out;

    float *p_qkv, *p_agent, *p_attn;
    cudaGetSymbolAddress((void**)&p_qkv, g_qkv);
    cudaGetSymbolAddress((void**)&p_agent, g_agent);
    cudaGetSymbolAddress((void**)&p_attn, g_attn);
    __nv_bfloat16 *p_xs, *p_as, *p_wqs, *p_wps;
    cudaGetSymbolAddress((void**)&p_xs, g_xs);
    cudaGetSymbolAddress((void**)&p_as, g_as);
    cudaGetSymbolAddress((void**)&p_wqs, g_wqs);
    cudaGetSymbolAddress((void**)&p_wps, g_wps);

    cudaFuncSetAttribute(gemm_mma, cudaFuncAttributeMaxDynamicSharedMemorySize,
                         GEMM_DSM);

    const int M = BATCH * NTOK;              // 50240
    const int MTILES = (M + 127) / 128;      // 393

    // 0) three-term bf16 splits of x and weights
    const int x8 = M * CH / 8;
    split3_a<<<(x8 + 255) / 256, 256>>>(x, p_xs, x8);
    const int wq8 = 3 * CH * CH / 8;
    split3_w<<<(wq8 + 255) / 256, 256>>>(w_qkv, p_wqs, wq8);
    const int wp8 = CH * CH / 8;
    split3_w<<<(wp8 + 255) / 256, 256>>>(w_proj, p_wps, wp8);

    // 1) QKV GEMM on tensor cores (mma.sync, 128x128 tiles, 4-stage)
    gemm_mma<<<MTILES * (3 * CH / 128), 256, GEMM_DSM>>>(
        p_xs, p_wqs, nullptr, p_qkv, M, 3 * CH);

    // 2) agent pooling
    pool_agent<<<dim3(AG, BATCH), 256>>>(p_agent);

    // 3/4) position biases
    build_pos1<<<NH * AG, 256>>>(an_b, ah_b, aw_b, ac_b);
    build_pos2<<<dim3(NTOK, NH), 64>>>(na_b, ha_b, wa_b, ca_b);

    // 5) stage-1 scores, fused softmax+AV
    s1_scores<<<BATCH * NH, 256>>>(p_agent);
    s1_av<<<BATCH * NH, 256>>>();

    // 6) stage-2 fused attention
    stage2<<<dim3((NTOK + 255) / 256, NH, BATCH), 256>>>(p_agent);

    // 7) depthwise conv add fused with proj-input split
    dwc_split<<<dim3(NTOK, BATCH), 256>>>(dwc_w, dwc_b);

    // 8) output projection on tensor cores
    gemm_mma<<<MTILES * (CH / 128), 256, GEMM_DSM>>>(
        p_as, p_wps, b_proj, out, M, CH);
}

// round 15
// speedup vs baseline: 1.1685x; 1.0076x over previous
#include <cuda_runtime.h>
#include <cuda_bf16.h>
#include <math.h>
#include <stdint.h>

// ---------------- problem constants ----------------
#define BATCH 64
#define NTOK  785          // 1 + 28*28
#define CH    768
#define NH    12
#define HD    64
#define AG    49
#define WIN   28
#define SCALE 0.125f       // hd^-0.5

// ---------------- scratch (device globals; no allocs allowed) ----------------
__device__ __align__(16) float g_qkv[(size_t)BATCH * NTOK * 3 * CH];   // (B,N,3C)
__device__ __align__(16) float g_agent[(size_t)BATCH * AG * CH];       // (B,A,C)
__device__ __align__(16) float g_agentv[(size_t)BATCH * NH * AG * HD]; // (B,H,A,hd)
__device__ __align__(16) float g_attn[(size_t)BATCH * NTOK * CH];      // stage2 output
__device__ __align__(16) float g_pos1[(size_t)NH * AG * NTOK];         // (H,A,N)
__device__ __align__(16) float g_pos2[(size_t)NH * NTOK * AG];         // (H,N,A)

// bf16 three-term split buffers (K tripled: 768 -> 2304)
// per original k: A' = {hi_a, lo_a, hi_a},  W' = {hi_w, hi_w, lo_w}
// => dot = hi*hi + lo_a*hi_w + hi_a*lo_w  (drops only lo*lo ~ 2^-18)
#define KT 2304
__device__ __align__(16) __nv_bfloat16 g_xs[(size_t)BATCH * NTOK * KT];   // x split (A pattern)
__device__ __align__(16) __nv_bfloat16 g_as[(size_t)BATCH * NTOK * KT];   // attn+dwc split (A pattern)
__device__ __align__(16) __nv_bfloat16 g_wqs[(size_t)(3 * CH) * KT];      // w_qkv split (W pattern)
__device__ __align__(16) __nv_bfloat16 g_wps[(size_t)CH * KT];            // w_proj split (W pattern)

// ================= PTX helpers (baseline ISA only: sm_80-class) =================
__device__ __forceinline__ uint32_t smem_u32(const void* p) {
    uint32_t a;
    asm("{ .reg .u64 t; cvta.to.shared.u64 t, %1; cvt.u32.u64 %0, t; }"
        : "=r"(a) : "l"(p));
    return a;
}
__device__ __forceinline__ void cpasync16(uint32_t dst, const void* src) {
    asm volatile("cp.async.cg.shared.global [%0], [%1], 16;" :: "r"(dst), "l"(src));
}
__device__ __forceinline__ void cpasync_commit() {
    asm volatile("cp.async.commit_group;" ::: "memory");
}
template <int N>
__device__ __forceinline__ void cpasync_wait() {
    asm volatile("cp.async.wait_group %0;" :: "n"(N) : "memory");
}
__device__ __forceinline__ void ldsm4(uint32_t* r, uint32_t addr) {
    asm volatile("ldmatrix.sync.aligned.m8n8.x4.shared.b16 {%0,%1,%2,%3}, [%4];"
                 : "=r"(r[0]), "=r"(r[1]), "=r"(r[2]), "=r"(r[3]) : "r"(addr));
}
__device__ __forceinline__ void mma16816(float* c, const uint32_t* a,
                                         uint32_t b0, uint32_t b1) {
    asm volatile(
        "mma.sync.aligned.m16n8k16.row.col.f32.bf16.bf16.f32 "
        "{%0,%1,%2,%3}, {%4,%5,%6,%7}, {%8,%9}, {%0,%1,%2,%3};"
        : "+f"(c[0]), "+f"(c[1]), "+f"(c[2]), "+f"(c[3])
        : "r"(a[0]), "r"(a[1]), "r"(a[2]), "r"(a[3]), "r"(b0), "r"(b1));
}

// ================= three-term splits =================
union Pack24 {
    __nv_bfloat16 h[24];
    uint4 q[3];
};

__global__ __launch_bounds__(256) void split3_a(
    const float* __restrict__ src, __nv_bfloat16* __restrict__ dst, int n8)
{
    int i = blockIdx.x * 256 + threadIdx.x;
    if (i >= n8) return;
    float4 v0 = ((const float4*)src)[2 * i];
    float4 v1 = ((const float4*)src)[2 * i + 1];
    float f[8] = {v0.x, v0.y, v0.z, v0.w, v1.x, v1.y, v1.z, v1.w};
    Pack24 o;
#pragma unroll
    for (int j = 0; j < 8; j++) {
        __nv_bfloat16 hi = __float2bfloat16(f[j]);
        __nv_bfloat16 lo = __float2bfloat16(f[j] - __bfloat162float(hi));
        o.h[3 * j] = hi; o.h[3 * j + 1] = lo; o.h[3 * j + 2] = hi;
    }
    uint4* d = (uint4*)(dst + (size_t)24 * i);
    d[0] = o.q[0]; d[1] = o.q[1]; d[2] = o.q[2];
}

__global__ __launch_bounds__(256) void split3_w(
    const float* __restrict__ src, __nv_bfloat16* __restrict__ dst, int n8)
{
    int i = blockIdx.x * 256 + threadIdx.x;
    if (i >= n8) return;
    float4 v0 = ((const float4*)src)[2 * i];
    float4 v1 = ((const float4*)src)[2 * i + 1];
    float f[8] = {v0.x, v0.y, v0.z, v0.w, v1.x, v1.y, v1.z, v1.w};
    Pack24 o;
#pragma unroll
    for (int j = 0; j < 8; j++) {
        __nv_bfloat16 hi = __float2bfloat16(f[j]);
        __nv_bfloat16 lo = __float2bfloat16(f[j] - __bfloat162float(hi));
        o.h[3 * j] = hi; o.h[3 * j + 1] = hi; o.h[3 * j + 2] = lo;
    }
    uint4* d = (uint4*)(dst + (size_t)24 * i);
    d[0] = o.q[0]; d[1] = o.q[1]; d[2] = o.q[2];
}

// ================= bf16-split tensor-core GEMM (mma.sync, 128x128, KC=64) =================
// C[m,n] = sum_k A'[m,k]*B'[n,k] (+bias[n]); A': M x KT bf16, B': Nw x KT bf16
#define KC 64                        // bf16 k per chunk
#define NCHUNK (KT / KC)             // 36
#define AST 72                       // padded smem row stride (bf16) = 144B rows
#define A_BYTES (128 * AST * 2)      // 18432 per stage
#define STAGE_BYTES (2 * A_BYTES)    // 36864 (A then B)
#define NSTAGE 3
#define GEMM_DSM (NSTAGE * STAGE_BYTES)   // 110592

__global__ __launch_bounds__(256, 2) void gemm_mma(
    const __nv_bfloat16* __restrict__ A, const __nv_bfloat16* __restrict__ Bw,
    const float* __restrict__ bias, float* __restrict__ C,
    int M, int Nw)
{
    extern __shared__ char dsm[];
    const uint32_t su = smem_u32(dsm);

    const int ntiles = Nw >> 7;
    const int m0 = (blockIdx.x / ntiles) << 7;
    const int n0 = (blockIdx.x % ntiles) << 7;
    const int tid = threadIdx.x;
    const int wid = tid >> 5, lane = tid & 31;
    const int wm = wid & 3, wn = wid >> 2;      // 4 x 2 warp grid; warp tile 32x64

    // ---- cp.async mapping: idx -> row = idx>>3 (0..127), 16B group = idx&7 ----
    const __nv_bfloat16* Ag[4];
    const __nv_bfloat16* Bg[4];
    uint32_t dA[4], dB[4];
#pragma unroll
    for (int i = 0; i < 4; i++) {
        int idx = tid + 256 * i;
        int row = idx >> 3, c = idx & 7;
        Ag[i] = A + (size_t)min(m0 + row, M - 1) * KT + c * 8;
        Bg[i] = Bw + (size_t)(n0 + row) * KT + c * 8;
        dA[i] = su + (uint32_t)(row * AST + c * 8) * 2;
        dB[i] = dA[i] + (uint32_t)A_BYTES;
    }

    // ---- ldmatrix base addresses (include su); per (ks,stage) adds immediates ----
    const int lrow16 = lane & 15;
    const int lk8 = (lane >> 4) << 3;
    uint32_t lA[2], lB[4];
#pragma unroll
    for (int mt = 0; mt < 2; mt++)
        lA[mt] = su + (uint32_t)(((wm * 32 + mt * 16 + lrow16) * AST) + lk8) * 2;
#pragma unroll
    for (int nt4 = 0; nt4 < 4; nt4++)
        lB[nt4] = su + (uint32_t)A_BYTES
                + (uint32_t)(((wn * 64 + nt4 * 16 + lrow16) * AST) + lk8) * 2;

    // prologue: stages 0..1
#pragma unroll
    for (int s = 0; s < NSTAGE - 1; s++) {
        int ko = s * KC;
#pragma unroll
        for (int i = 0; i < 4; i++) {
            cpasync16(dA[i] + s * STAGE_BYTES, Ag[i] + ko);
            cpasync16(dB[i] + s * STAGE_BYTES, Bg[i] + ko);
        }
        cpasync_commit();
    }

    float acc[2][8][4];
#pragma unroll
    for (int mt = 0; mt < 2; mt++)
#pragma unroll
        for (int nt = 0; nt < 8; nt++)
#pragma unroll
            for (int q = 0; q < 4; q++) acc[mt][nt][q] = 0.f;

    for (int c0 = 0; c0 < NCHUNK; c0 += NSTAGE) {
#pragma unroll
        for (int s = 0; s < NSTAGE; s++) {
            const int c = c0 + s;
            cpasync_wait<NSTAGE - 2>();
            __syncthreads();
            // prefetch into stage (s+2)%3 = chunk c-1's stage; its compute
            // finished before the barrier above.
            const int pf = c + NSTAGE - 1;
            const uint32_t pso = ((s + NSTAGE - 1) % NSTAGE) * STAGE_BYTES;
            if (pf < NCHUNK) {
                int ko = pf * KC;
#pragma unroll
                for (int i = 0; i < 4; i++) {
                    cpasync16(dA[i] + pso, Ag[i] + ko);
                    cpasync16(dB[i] + pso, Bg[i] + ko);
                }
            }
            cpasync_commit();

            const uint32_t so = s * STAGE_BYTES;    // compile-time
#pragma unroll
            for (int ks = 0; ks < 4; ks++) {
                const uint32_t kso = so + ks * 32;  // ks*16 bf16 = 32B
                uint32_t af[2][4];
#pragma unroll
                for (int mt = 0; mt < 2; mt++)
                    ldsm4(af[mt], lA[mt] + kso);
                uint32_t bf[4][4];
#pragma unroll
                for (int nt4 = 0; nt4 < 4; nt4++)
                    ldsm4(bf[nt4], lB[nt4] + kso);
#pragma unroll
                for (int mt = 0; mt < 2; mt++)
#pragma unroll
                    for (int nt4 = 0; nt4 < 4; nt4++) {
                        mma16816(acc[mt][nt4 * 2 + 0], af[mt], bf[nt4][0], bf[nt4][2]);
                        mma16816(acc[mt][nt4 * 2 + 1], af[mt], bf[nt4][1], bf[nt4][3]);
                    }
            }
        }
    }

    // ---- epilogue ----
#pragma unroll
    for (int mt = 0; mt < 2; mt++) {
        int r0 = m0 + wm * 32 + mt * 16 + (lane >> 2);
        int r1 = r0 + 8;
#pragma unroll
        for (int nt = 0; nt < 8; nt++) {
            int col = n0 + wn * 64 + nt * 8 + (lane & 3) * 2;
            float b0 = 0.f, b1 = 0.f;
            if (bias) { b0 = bias[col]; b1 = bias[col + 1]; }
            if (r0 < M) {
                float2 o; o.x = acc[mt][nt][0] + b0; o.y = acc[mt][nt][1] + b1;
                *(float2*)(C + (size_t)r0 * Nw + col) = o;
            }
            if (r1 < M) {
                float2 o; o.x = acc[mt][nt][2] + b0; o.y = acc[mt][nt][3] + b1;
                *(float2*)(C + (size_t)r1 * Nw + col) = o;
            }
        }
    }
}

// ---------------- agent pooling: 28x28 q image tokens -> 7x7 avg ----------------
__global__ __launch_bounds__(256) void pool_agent(float* __restrict__ agent)
{
    const int a = blockIdx.x;
    const int b = blockIdx.y;
    const int pr = a / 7, pc = a % 7;
    for (int c = threadIdx.x; c < CH; c += 256) {
        float s = 0.f;
#pragma unroll
        for (int i = 0; i < 4; i++)
#pragma unroll
            for (int j = 0; j < 4; j++) {
                int tok = 1 + (pr * 4 + i) * WIN + (pc * 4 + j);
                s += g_qkv[((size_t)(b * NTOK + tok)) * (3 * CH) + c];
            }
        agent[((size_t)b * AG + a) * CH + c] = s * (1.f / 16.f);
    }
}

// ---------------- jax bilinear (half-pixel upsample => clamped bilinear) ----------------
__device__ __forceinline__ float bilin7(const float* __restrict__ p, int r, int c)
{
    float fy = (r + 0.5f) * 0.25f - 0.5f;
    float fx = (c + 0.5f) * 0.25f - 0.5f;
    int y0 = (int)floorf(fy); float wy = fy - (float)y0;
    int x0 = (int)floorf(fx); float wx = fx - (float)x0;
    int y0c = min(max(y0, 0), 6), y1c = min(max(y0 + 1, 0), 6);
    int x0c = min(max(x0, 0), 6), x1c = min(max(x0 + 1, 0), 6);
    float v00 = p[y0c * 7 + x0c], v01 = p[y0c * 7 + x1c];
    float v10 = p[y1c * 7 + x0c], v11 = p[y1c * 7 + x1c];
    return (1.f - wy) * ((1.f - wx) * v00 + wx * v01)
         + wy * ((1.f - wx) * v10 + wx * v11);
}

__global__ __launch_bounds__(256) void build_pos1(
    const float* __restrict__ an, const float* __restrict__ ah,
    const float* __restrict__ aw, const float* __restrict__ ac)
{
    const int h = blockIdx.x / AG, a = blockIdx.x % AG;
    const float* anp = an + ((size_t)h * AG + a) * 49;
    float* out = g_pos1 + ((size_t)h * AG + a) * NTOK;
    if (threadIdx.x == 0) out[0] = ac[h * AG + a];
    for (int t = threadIdx.x; t < WIN * WIN; t += 256) {
        int r = t / WIN, c = t % WIN;
        out[1 + t] = bilin7(anp, r, c)
                   + ah[((size_t)h * AG + a) * WIN + r]
                   + aw[((size_t)h * AG + a) * WIN + c];
    }
}

__global__ __launch_bounds__(64) void build_pos2(
    const float* __restrict__ na, const float* __restrict__ ha,
    const float* __restrict__ wa, const float* __restrict__ ca)
{
    const int n = blockIdx.x;
    const int h = blockIdx.y;
    const int a = threadIdx.x;
    if (a >= AG) return;
    float v;
    if (n == 0) {
        v = ca[h * AG + a];
    } else {
        int t = n - 1, r = t / WIN, c = t % WIN;
        v = bilin7(na + ((size_t)h * AG + a) * 49, r, c)
          + ha[(size_t)h * WIN * AG + (size_t)r * AG + a]
          + wa[(size_t)h * WIN * AG + (size_t)c * AG + a];
    }
    g_pos2[((size_t)h * NTOK + n) * AG + a] = v;
}

// ---------------- stage 1 FUSED: scores -> softmax -> agent_v, scores in smem ----------------
// smem floats (all region starts padded to 16B):
//   sc[49*785] | buf[4096] (agt then sv) | sp[49*64] | smx[49] | sinv[49]
#define S1_SC    0
#define S1_BUF   38468                       // AG*NTOK=38465 padded to mult of 4
#define S1_SP    (S1_BUF + 4096)             // 42564 (mult of 4)
#define S1_SMX   (S1_SP + AG * 64)           // 45700
#define S1_SINV  (S1_SMX + AG + 3)           // 45752 (mult of 4)
#define S1_FLTS  (S1_SINV + AG + 3)          // 45804
#define S1_DSM   (S1_FLTS * 4)               // 183216 bytes

__global__ __launch_bounds__(512) void s1_fused(const float* __restrict__ agent)
{
    extern __shared__ float sm[];
    float* sc  = sm + S1_SC;
    float* buf = sm + S1_BUF;
    float* sp  = sm + S1_SP;
    float* smx = sm + S1_SMX;
    float* sinv= sm + S1_SINV;

    const int b = blockIdx.x / NH, h = blockIdx.x % NH;
    const int tid = threadIdx.x;
    const int wid = tid >> 5, lane = tid & 31;

    // agt into buf (49 x 64), pre-scaled
    for (int i = tid; i < AG * HD; i += 512) {
        int a = i >> 6, d = i & 63;
        buf[i] = agent[((size_t)b * AG + a) * CH + h * HD + d] * SCALE;
    }
    __syncthreads();

    // phase A: scores into smem
    const float* pb = g_pos1 + (size_t)h * AG * NTOK;
    for (int n = tid; n < NTOK; n += 512) {
        const float* kp = g_qkv + ((size_t)(b * NTOK + n)) * (3 * CH) + CH + h * HD;
        float kr[HD];
#pragma unroll
        for (int d = 0; d < HD; d += 4) {
            float4 t = *(const float4*)(kp + d);
            kr[d] = t.x; kr[d + 1] = t.y; kr[d + 2] = t.z; kr[d + 3] = t.w;
        }
#pragma unroll 1
        for (int a = 0; a < AG; a++) {
            const float4* ap = (const float4*)(buf + a * HD);
            float acc = 0.f;
#pragma unroll
            for (int q = 0; q < HD / 4; q++) {
                float4 av = ap[q];
                acc += av.x * kr[4 * q] + av.y * kr[4 * q + 1]
                     + av.z * kr[4 * q + 2] + av.w * kr[4 * q + 3];
            }
            sc[a * NTOK + n] = acc + pb[(size_t)a * NTOK + n];
        }
    }
    __syncthreads();

    // phase B: per-agent max & sum (warp per agent; 16 warps)
    for (int a = wid; a < AG; a += 16) {
        const float* row = sc + a * NTOK;
        float mx = -1e30f;
        for (int n = lane; n < NTOK; n += 32) mx = fmaxf(mx, row[n]);
#pragma unroll
        for (int o = 16; o > 0; o >>= 1)
            mx = fmaxf(mx, __shfl_xor_sync(0xFFFFFFFFu, mx, o));
        float smv = 0.f;
        for (int n = lane; n < NTOK; n += 32) smv += expf(row[n] - mx);
#pragma unroll
        for (int o = 16; o > 0; o >>= 1)
            smv += __shfl_xor_sync(0xFFFFFFFFu, smv, o);
        if (lane == 0) { smx[a] = mx; sinv[a] = 1.f / smv; }
    }
    __syncthreads();

    // phase C: agent_v accumulation (buf reused as sv 64x64)
    float* sv = buf;
    const int d = tid & 63;
    const int a0 = tid >> 6;          // 0..7
    float acc[7];
#pragma unroll
    for (int i = 0; i < 7; i++) acc[i] = 0.f;

    for (int n0 = 0; n0 < NTOK; n0 += 64) {
        int nt = min(64, NTOK - n0);
        __syncthreads();
        for (int i = tid; i < nt * 64; i += 512) {
            int nn = i >> 6, dd = i & 63;
            sv[i] = g_qkv[((size_t)(b * NTOK + n0 + nn)) * (3 * CH) + 2 * CH + h * HD + dd];
        }
        for (int i = tid; i < AG * 64; i += 512) {
            int a = i >> 6, nn = i & 63;
            if (nn < nt)
                sp[i] = expf(sc[a * NTOK + n0 + nn] - smx[a]);
        }
        __syncthreads();
        for (int nn = 0; nn < nt; nn++) {
            float vv = sv[nn * 64 + d];
#pragma unroll
            for (int i = 0; i < 7; i++) {
                int a = a0 + 8 * i;
                if (a < AG) acc[i] += sp[a * 64 + nn] * vv;
            }
        }
    }
#pragma unroll
    for (int i = 0; i < 7; i++) {
        int a = a0 + 8 * i;
        if (a < AG)
            g_agentv[((size_t)(b * NH + h) * AG + a) * HD + d] = acc[i] * sinv[a];
    }
}

// ---------------- stage 2 fused ----------------
__global__ __launch_bounds__(256) void stage2(const float* __restrict__ agent)
{
    const int h = blockIdx.y, b = blockIdx.z;
    __shared__ __align__(16) float agt[AG][HD];
    __shared__ __align__(16) float sv[AG][HD];
    for (int i = threadIdx.x; i < AG * HD; i += 256) {
        int a = i / HD, d = i % HD;
        agt[a][d] = agent[((size_t)b * AG + a) * CH + h * HD + d] * SCALE;
        sv[a][d]  = g_agentv[((size_t)(b * NH + h) * AG + a) * HD + d];
    }
    __syncthreads();

    const int n = blockIdx.x * 256 + threadIdx.x;
    if (n >= NTOK) return;

    float qr[HD];
    const float* qp = g_qkv + ((size_t)(b * NTOK + n)) * (3 * CH) + h * HD;
#pragma unroll
    for (int dd = 0; dd < HD; dd += 4) {
        float4 t = *(const float4*)(qp + dd);
        qr[dd] = t.x; qr[dd + 1] = t.y; qr[dd + 2] = t.z; qr[dd + 3] = t.w;
    }

    const float* pb = g_pos2 + ((size_t)h * NTOK + n) * AG;
    float sc[AG];
    float mx = -1e30f;
#pragma unroll 1
    for (int a = 0; a < AG; a++) {
        const float4* ap = (const float4*)agt[a];
        float acc = 0.f;
#pragma unroll
        for (int q = 0; q < HD / 4; q++) {
            float4 av = ap[q];
            acc += av.x * qr[4 * q] + av.y * qr[4 * q + 1]
                 + av.z * qr[4 * q + 2] + av.w * qr[4 * q + 3];
        }
        sc[a] = acc + pb[a];
        mx = fmaxf(mx, sc[a]);
    }
    float sum = 0.f;
#pragma unroll
    for (int a = 0; a < AG; a++) {
        float e = expf(sc[a] - mx);
        sc[a] = e; sum += e;
    }
    float inv = 1.f / sum;
#pragma unroll
    for (int a = 0; a < AG; a++) sc[a] *= inv;

    float od[HD];
#pragma unroll
    for (int dd = 0; dd < HD; dd++) od[dd] = 0.f;
#pragma unroll 1
    for (int a = 0; a < AG; a++) {
        float w = sc[a];
        const float4* vp = (const float4*)sv[a];
#pragma unroll
        for (int q = 0; q < HD / 4; q++) {
            float4 t = vp[q];
            od[4 * q]     += w * t.x; od[4 * q + 1] += w * t.y;
            od[4 * q + 2] += w * t.z; od[4 * q + 3] += w * t.w;
        }
    }
    float* op = g_attn + ((size_t)(b * NTOK + n)) * CH + h * HD;
#pragma unroll
    for (int dd = 0; dd < HD; dd += 4) {
        float4 t;
        t.x = od[dd]; t.y = od[dd + 1]; t.z = od[dd + 2]; t.w = od[dd + 3];
        *(float4*)(op + dd) = t;
    }
}

// ---------------- fused: depthwise conv add + three-term split into g_as ----------------
__global__ __launch_bounds__(256) void dwc_split(
    const float* __restrict__ w, const float* __restrict__ bias)
{
    const int t = blockIdx.x;          // 0..784 token index
    const int b = blockIdx.y;
    const float* src = g_attn + ((size_t)(b * NTOK + t)) * CH;
    __nv_bfloat16* dst = g_as + ((size_t)(b * NTOK + t)) * KT;

    if (t == 0) {
        for (int c = threadIdx.x; c < CH; c += 256) {
            float v = src[c];
            __nv_bfloat16 hi = __float2bfloat16(v);
            __nv_bfloat16 lo = __float2bfloat16(v - __bfloat162float(hi));
            dst[3 * c] = hi; dst[3 * c + 1] = lo; dst[3 * c + 2] = hi;
        }
        return;
    }
    const int ti = t - 1;
    const int r = ti / WIN, cc = ti % WIN;
    for (int c = threadIdx.x; c < CH; c += 256) {
        float acc = bias[c] + src[c];
#pragma unroll
        for (int ky = 0; ky < 3; ky++) {
            int rr = r + ky - 1;
            if (rr < 0 || rr >= WIN) continue;
#pragma unroll
            for (int kx = 0; kx < 3; kx++) {
                int c2 = cc + kx - 1;
                if (c2 < 0 || c2 >= WIN) continue;
                acc += w[(ky * 3 + kx) * CH + c]
                     * g_qkv[((size_t)(b * NTOK + 1 + rr * WIN + c2)) * (3 * CH) + 2 * CH + c];
            }
        }
        __nv_bfloat16 hi = __float2bfloat16(acc);
        __nv_bfloat16 lo = __float2bfloat16(acc - __bfloat162float(hi));
        dst[3 * c] = hi; dst[3 * c + 1] = lo; dst[3 * c + 2] = hi;
    }
}

// ---------------- launch ----------------
extern "C" void kernel_launch(void* const* d_in, const int* in_sizes, int n_in,
                              void* d_out, int out_size)
{
    const float* x      = (const float*)d_in[0];
    const float* w_qkv  = (const float*)d_in[1];
    const float* w_proj = (const float*)d_in[2];
    const float* b_proj = (const float*)d_in[3];
    const float* dwc_w  = (const float*)d_in[4];
    const float* dwc_b  = (const float*)d_in[5];
    const float* an_b   = (const float*)d_in[6];
    const float* ah_b   = (const float*)d_in[7];
    const float* aw_b   = (const float*)d_in[8];
    const float* na_b   = (const float*)d_in[9];
    const float* ha_b   = (const float*)d_in[10];
    const float* wa_b   = (const float*)d_in[11];
    const float* ac_b   = (const float*)d_in[12];
    const float* ca_b   = (const float*)d_in[13];
    float* out = (float*)d_out;

    float *p_qkv, *p_agent, *p_attn;
    cudaGetSymbolAddress((void**)&p_qkv, g_qkv);
    cudaGetSymbolAddress((void**)&p_agent, g_agent);
    cudaGetSymbolAddress((void**)&p_attn, g_attn);
    __nv_bfloat16 *p_xs, *p_as, *p_wqs, *p_wps;
    cudaGetSymbolAddress((void**)&p_xs, g_xs);
    cudaGetSymbolAddress((void**)&p_as, g_as);
    cudaGetSymbolAddress((void**)&p_wqs, g_wqs);
    cudaGetSymbolAddress((void**)&p_wps, g_wps);

    cudaFuncSetAttribute(gemm_mma, cudaFuncAttributeMaxDynamicSharedMemorySize,
                         GEMM_DSM);
    cudaFuncSetAttribute(s1_fused, cudaFuncAttributeMaxDynamicSharedMemorySize,
                         S1_DSM);

    const int M = BATCH * NTOK;              // 50240
    const int MTILES = (M + 127) / 128;      // 393

    // 0) three-term bf16 splits of x and weights
    const int x8 = M * CH / 8;
    split3_a<<<(x8 + 255) / 256, 256>>>(x, p_xs, x8);
    const int wq8 = 3 * CH * CH / 8;
    split3_w<<<(wq8 + 255) / 256, 256>>>(w_qkv, p_wqs, wq8);
    const int wp8 = CH * CH / 8;
    split3_w<<<(wp8 + 255) / 256, 256>>>(w_proj, p_wps, wp8);

    // 1) QKV GEMM on tensor cores (mma.sync, 128x128 tiles, KC=64, 3-stage)
    gemm_mma<<<MTILES * (3 * CH / 128), 256, GEMM_DSM>>>(
        p_xs, p_wqs, nullptr, p_qkv, M, 3 * CH);

    // 2) agent pooling
    pool_agent<<<dim3(AG, BATCH), 256>>>(p_agent);

    // 3/4) position biases
    build_pos1<<<NH * AG, 256>>>(an_b, ah_b, aw_b, ac_b);
    build_pos2<<<dim3(NTOK, NH), 64>>>(na_b, ha_b, wa_b, ca_b);

    // 5) stage-1 fully fused (scores + softmax + AV, scores in smem)
    s1_fused<<<BATCH * NH, 512, S1_DSM>>>(p_agent);

    // 6) stage-2 fused attention
    stage2<<<dim3((NTOK + 255) / 256, NH, BATCH), 256>>>(p_agent);

    // 7) depthwise conv add fused with proj-input split
    dwc_split<<<dim3(NTOK, BATCH), 256>>>(dwc_w, dwc_b);

    // 8) output projection on tensor cores
    gemm_mma<<<MTILES * (CH / 128), 256, GEMM_DSM>>>(
        p_as, p_wps, b_proj, out, M, CH);
}

// round 16
// speedup vs baseline: 1.1963x; 1.0238x over previous
#include <cuda_runtime.h>
#include <cuda_bf16.h>
#include <math.h>
#include <stdint.h>

// ---------------- problem constants ----------------
#define BATCH 64
#define NTOK  785          // 1 + 28*28
#define CH    768
#define NH    12
#define HD    64
#define AG    49
#define WIN   28
#define SCALE 0.125f       // hd^-0.5

// ---------------- scratch (device globals; no allocs allowed) ----------------
__device__ __align__(16) float g_qkv[(size_t)BATCH * NTOK * 3 * CH];   // (B,N,3C)
__device__ __align__(16) float g_agent[(size_t)BATCH * AG * CH];       // (B,A,C)
__device__ __align__(16) float g_agentv[(size_t)BATCH * NH * AG * HD]; // (B,H,A,hd)
__device__ __align__(16) float g_attn[(size_t)BATCH * NTOK * CH];      // stage2 output
__device__ __align__(16) float g_pos1[(size_t)NH * AG * NTOK];         // (H,A,N)
__device__ __align__(16) float g_pos2[(size_t)NH * NTOK * AG];         // (H,N,A)
__device__ __align__(16) float g_s1[(size_t)BATCH * NH * AG * NTOK];   // stage-1 raw scores

// bf16 three-term split buffers (K tripled: 768 -> 2304)
// per original k: A' = {hi_a, lo_a, hi_a},  W' = {hi_w, hi_w, lo_w}
// => dot = hi*hi + lo_a*hi_w + hi_a*lo_w  (drops only lo*lo ~ 2^-18)
#define KT 2304
__device__ __align__(16) __nv_bfloat16 g_xs[(size_t)BATCH * NTOK * KT];   // x split (A pattern)
__device__ __align__(16) __nv_bfloat16 g_as[(size_t)BATCH * NTOK * KT];   // attn+dwc split (A pattern)
__device__ __align__(16) __nv_bfloat16 g_wqs[(size_t)(3 * CH) * KT];      // w_qkv split (W pattern)
__device__ __align__(16) __nv_bfloat16 g_wps[(size_t)CH * KT];            // w_proj split (W pattern)

// ================= PTX helpers (baseline ISA only: sm_80-class) =================
__device__ __forceinline__ uint32_t smem_u32(const void* p) {
    uint32_t a;
    asm("{ .reg .u64 t; cvta.to.shared.u64 t, %1; cvt.u32.u64 %0, t; }"
        : "=r"(a) : "l"(p));
    return a;
}
__device__ __forceinline__ void cpasync16(uint32_t dst, const void* src) {
    asm volatile("cp.async.cg.shared.global [%0], [%1], 16;" :: "r"(dst), "l"(src));
}
__device__ __forceinline__ void cpasync_commit() {
    asm volatile("cp.async.commit_group;" ::: "memory");
}
template <int N>
__device__ __forceinline__ void cpasync_wait() {
    asm volatile("cp.async.wait_group %0;" :: "n"(N) : "memory");
}
__device__ __forceinline__ void ldsm4(uint32_t* r, uint32_t addr) {
    asm volatile("ldmatrix.sync.aligned.m8n8.x4.shared.b16 {%0,%1,%2,%3}, [%4];"
                 : "=r"(r[0]), "=r"(r[1]), "=r"(r[2]), "=r"(r[3]) : "r"(addr));
}
__device__ __forceinline__ void mma16816(float* c, const uint32_t* a,
                                         uint32_t b0, uint32_t b1) {
    asm volatile(
        "mma.sync.aligned.m16n8k16.row.col.f32.bf16.bf16.f32 "
        "{%0,%1,%2,%3}, {%4,%5,%6,%7}, {%8,%9}, {%0,%1,%2,%3};"
        : "+f"(c[0]), "+f"(c[1]), "+f"(c[2]), "+f"(c[3])
        : "r"(a[0]), "r"(a[1]), "r"(a[2]), "r"(a[3]), "r"(b0), "r"(b1));
}

// ================= three-term splits =================
union Pack24 {
    __nv_bfloat16 h[24];
    uint4 q[3];
};

__global__ __launch_bounds__(256) void split3_a(
    const float* __restrict__ src, __nv_bfloat16* __restrict__ dst, int n8)
{
    int i = blockIdx.x * 256 + threadIdx.x;
    if (i >= n8) return;
    float4 v0 = ((const float4*)src)[2 * i];
    float4 v1 = ((const float4*)src)[2 * i + 1];
    float f[8] = {v0.x, v0.y, v0.z, v0.w, v1.x, v1.y, v1.z, v1.w};
    Pack24 o;
#pragma unroll
    for (int j = 0; j < 8; j++) {
        __nv_bfloat16 hi = __float2bfloat16(f[j]);
        __nv_bfloat16 lo = __float2bfloat16(f[j] - __bfloat162float(hi));
        o.h[3 * j] = hi; o.h[3 * j + 1] = lo; o.h[3 * j + 2] = hi;
    }
    uint4* d = (uint4*)(dst + (size_t)24 * i);
    d[0] = o.q[0]; d[1] = o.q[1]; d[2] = o.q[2];
}

__global__ __launch_bounds__(256) void split3_w(
    const float* __restrict__ src, __nv_bfloat16* __restrict__ dst, int n8)
{
    int i = blockIdx.x * 256 + threadIdx.x;
    if (i >= n8) return;
    float4 v0 = ((const float4*)src)[2 * i];
    float4 v1 = ((const float4*)src)[2 * i + 1];
    float f[8] = {v0.x, v0.y, v0.z, v0.w, v1.x, v1.y, v1.z, v1.w};
    Pack24 o;
#pragma unroll
    for (int j = 0; j < 8; j++) {
        __nv_bfloat16 hi = __float2bfloat16(f[j]);
        __nv_bfloat16 lo = __float2bfloat16(f[j] - __bfloat162float(hi));
        o.h[3 * j] = hi; o.h[3 * j + 1] = hi; o.h[3 * j + 2] = lo;
    }
    uint4* d = (uint4*)(dst + (size_t)24 * i);
    d[0] = o.q[0]; d[1] = o.q[1]; d[2] = o.q[2];
}

// ================= bf16-split tensor-core GEMM (mma.sync, 128x128, KC=64) =================
// C[m,n] = sum_k A'[m,k]*B'[n,k] (+bias[n]); A': M x KT bf16, B': Nw x KT bf16
#define KC 64                        // bf16 k per chunk
#define NCHUNK (KT / KC)             // 36
#define AST 72                       // padded smem row stride (bf16) = 144B rows
#define A_BYTES (128 * AST * 2)      // 18432 per stage
#define STAGE_BYTES (2 * A_BYTES)    // 36864 (A then B)
#define NSTAGE 3
#define GEMM_DSM (NSTAGE * STAGE_BYTES)   // 110592

__global__ __launch_bounds__(256, 2) void gemm_mma(
    const __nv_bfloat16* __restrict__ A, const __nv_bfloat16* __restrict__ Bw,
    const float* __restrict__ bias, float* __restrict__ C,
    int M, int Nw)
{
    extern __shared__ char dsm[];
    const uint32_t su = smem_u32(dsm);

    const int ntiles = Nw >> 7;
    const int m0 = (blockIdx.x / ntiles) << 7;
    const int n0 = (blockIdx.x % ntiles) << 7;
    const int tid = threadIdx.x;
    const int wid = tid >> 5, lane = tid & 31;
    const int wm = wid & 3, wn = wid >> 2;      // 4 x 2 warp grid; warp tile 32x64

    // ---- cp.async mapping: idx -> row = idx>>3 (0..127), 16B group = idx&7 ----
    const __nv_bfloat16* Ag[4];
    const __nv_bfloat16* Bg[4];
    uint32_t dA[4], dB[4];
#pragma unroll
    for (int i = 0; i < 4; i++) {
        int idx = tid + 256 * i;
        int row = idx >> 3, c = idx & 7;
        Ag[i] = A + (size_t)min(m0 + row, M - 1) * KT + c * 8;
        Bg[i] = Bw + (size_t)(n0 + row) * KT + c * 8;
        dA[i] = su + (uint32_t)(row * AST + c * 8) * 2;
        dB[i] = dA[i] + (uint32_t)A_BYTES;
    }

    // ---- ldmatrix base addresses (include su); per (ks,stage) adds immediates ----
    const int lrow16 = lane & 15;
    const int lk8 = (lane >> 4) << 3;
    uint32_t lA[2], lB[4];
#pragma unroll
    for (int mt = 0; mt < 2; mt++)
        lA[mt] = su + (uint32_t)(((wm * 32 + mt * 16 + lrow16) * AST) + lk8) * 2;
#pragma unroll
    for (int nt4 = 0; nt4 < 4; nt4++)
        lB[nt4] = su + (uint32_t)A_BYTES
                + (uint32_t)(((wn * 64 + nt4 * 16 + lrow16) * AST) + lk8) * 2;

    // prologue: stages 0..1
#pragma unroll
    for (int s = 0; s < NSTAGE - 1; s++) {
        int ko = s * KC;
#pragma unroll
        for (int i = 0; i < 4; i++) {
            cpasync16(dA[i] + s * STAGE_BYTES, Ag[i] + ko);
            cpasync16(dB[i] + s * STAGE_BYTES, Bg[i] + ko);
        }
        cpasync_commit();
    }

    float acc[2][8][4];
#pragma unroll
    for (int mt = 0; mt < 2; mt++)
#pragma unroll
        for (int nt = 0; nt < 8; nt++)
#pragma unroll
            for (int q = 0; q < 4; q++) acc[mt][nt][q] = 0.f;

    for (int c0 = 0; c0 < NCHUNK; c0 += NSTAGE) {
#pragma unroll
        for (int s = 0; s < NSTAGE; s++) {
            const int c = c0 + s;
            cpasync_wait<NSTAGE - 2>();
            __syncthreads();
            // prefetch into stage (s+2)%3 = chunk c-1's stage; its compute
            // finished before the barrier above.
            const int pf = c + NSTAGE - 1;
            const uint32_t pso = ((s + NSTAGE - 1) % NSTAGE) * STAGE_BYTES;
            if (pf < NCHUNK) {
                int ko = pf * KC;
#pragma unroll
                for (int i = 0; i < 4; i++) {
                    cpasync16(dA[i] + pso, Ag[i] + ko);
                    cpasync16(dB[i] + pso, Bg[i] + ko);
                }
            }
            cpasync_commit();

            const uint32_t so = s * STAGE_BYTES;    // compile-time
#pragma unroll
            for (int ks = 0; ks < 4; ks++) {
                const uint32_t kso = so + ks * 32;  // ks*16 bf16 = 32B
                uint32_t af[2][4];
#pragma unroll
                for (int mt = 0; mt < 2; mt++)
                    ldsm4(af[mt], lA[mt] + kso);
                uint32_t bf[4][4];
#pragma unroll
                for (int nt4 = 0; nt4 < 4; nt4++)
                    ldsm4(bf[nt4], lB[nt4] + kso);
#pragma unroll
                for (int mt = 0; mt < 2; mt++)
#pragma unroll
                    for (int nt4 = 0; nt4 < 4; nt4++) {
                        mma16816(acc[mt][nt4 * 2 + 0], af[mt], bf[nt4][0], bf[nt4][2]);
                        mma16816(acc[mt][nt4 * 2 + 1], af[mt], bf[nt4][1], bf[nt4][3]);
                    }
            }
        }
    }

    // ---- epilogue ----
#pragma unroll
    for (int mt = 0; mt < 2; mt++) {
        int r0 = m0 + wm * 32 + mt * 16 + (lane >> 2);
        int r1 = r0 + 8;
#pragma unroll
        for (int nt = 0; nt < 8; nt++) {
            int col = n0 + wn * 64 + nt * 8 + (lane & 3) * 2;
            float b0 = 0.f, b1 = 0.f;
            if (bias) { b0 = bias[col]; b1 = bias[col + 1]; }
            if (r0 < M) {
                float2 o; o.x = acc[mt][nt][0] + b0; o.y = acc[mt][nt][1] + b1;
                *(float2*)(C + (size_t)r0 * Nw + col) = o;
            }
            if (r1 < M) {
                float2 o; o.x = acc[mt][nt][2] + b0; o.y = acc[mt][nt][3] + b1;
                *(float2*)(C + (size_t)r1 * Nw + col) = o;
            }
        }
    }
}

// ---------------- agent pooling: 28x28 q image tokens -> 7x7 avg ----------------
__global__ __launch_bounds__(256) void pool_agent(float* __restrict__ agent)
{
    const int a = blockIdx.x;
    const int b = blockIdx.y;
    const int pr = a / 7, pc = a % 7;
    for (int c = threadIdx.x; c < CH; c += 256) {
        float s = 0.f;
#pragma unroll
        for (int i = 0; i < 4; i++)
#pragma unroll
            for (int j = 0; j < 4; j++) {
                int tok = 1 + (pr * 4 + i) * WIN + (pc * 4 + j);
                s += g_qkv[((size_t)(b * NTOK + tok)) * (3 * CH) + c];
            }
        agent[((size_t)b * AG + a) * CH + c] = s * (1.f / 16.f);
    }
}

// ---------------- jax bilinear (half-pixel upsample => clamped bilinear) ----------------
__device__ __forceinline__ float bilin7(const float* __restrict__ p, int r, int c)
{
    float fy = (r + 0.5f) * 0.25f - 0.5f;
    float fx = (c + 0.5f) * 0.25f - 0.5f;
    int y0 = (int)floorf(fy); float wy = fy - (float)y0;
    int x0 = (int)floorf(fx); float wx = fx - (float)x0;
    int y0c = min(max(y0, 0), 6), y1c = min(max(y0 + 1, 0), 6);
    int x0c = min(max(x0, 0), 6), x1c = min(max(x0 + 1, 0), 6);
    float v00 = p[y0c * 7 + x0c], v01 = p[y0c * 7 + x1c];
    float v10 = p[y1c * 7 + x0c], v11 = p[y1c * 7 + x1c];
    return (1.f - wy) * ((1.f - wx) * v00 + wx * v01)
         + wy * ((1.f - wx) * v10 + wx * v11);
}

__global__ __launch_bounds__(256) void build_pos1(
    const float* __restrict__ an, const float* __restrict__ ah,
    const float* __restrict__ aw, const float* __restrict__ ac)
{
    const int h = blockIdx.x / AG, a = blockIdx.x % AG;
    const float* anp = an + ((size_t)h * AG + a) * 49;
    float* out = g_pos1 + ((size_t)h * AG + a) * NTOK;
    if (threadIdx.x == 0) out[0] = ac[h * AG + a];
    for (int t = threadIdx.x; t < WIN * WIN; t += 256) {
        int r = t / WIN, c = t % WIN;
        out[1 + t] = bilin7(anp, r, c)
                   + ah[((size_t)h * AG + a) * WIN + r]
                   + aw[((size_t)h * AG + a) * WIN + c];
    }
}

__global__ __launch_bounds__(64) void build_pos2(
    const float* __restrict__ na, const float* __restrict__ ha,
    const float* __restrict__ wa, const float* __restrict__ ca)
{
    const int n = blockIdx.x;
    const int h = blockIdx.y;
    const int a = threadIdx.x;
    if (a >= AG) return;
    float v;
    if (n == 0) {
        v = ca[h * AG + a];
    } else {
        int t = n - 1, r = t / WIN, c = t % WIN;
        v = bilin7(na + ((size_t)h * AG + a) * 49, r, c)
          + ha[(size_t)h * WIN * AG + (size_t)r * AG + a]
          + wa[(size_t)h * WIN * AG + (size_t)c * AG + a];
    }
    g_pos2[((size_t)h * NTOK + n) * AG + a] = v;
}

// ---------------- stage 1: scores = scale*agent @ k^T + pos1 (raw) ----------------
__global__ __launch_bounds__(256) void s1_scores(const float* __restrict__ agent)
{
    const int b = blockIdx.x / NH, h = blockIdx.x % NH;
    __shared__ __align__(16) float agt[AG][HD];
    for (int i = threadIdx.x; i < AG * HD; i += 256) {
        int a = i / HD, d = i % HD;
        agt[a][d] = agent[((size_t)b * AG + a) * CH + h * HD + d] * SCALE;
    }
    __syncthreads();
    const float* pb = g_pos1 + (size_t)h * AG * NTOK;
    for (int n = threadIdx.x; n < NTOK; n += 256) {
        const float* kp = g_qkv + ((size_t)(b * NTOK + n)) * (3 * CH) + CH + h * HD;
        float kr[HD];
#pragma unroll
        for (int d = 0; d < HD; d += 4) {
            float4 t = *(const float4*)(kp + d);
            kr[d] = t.x; kr[d + 1] = t.y; kr[d + 2] = t.z; kr[d + 3] = t.w;
        }
        float* sout = g_s1 + ((size_t)(b * NH + h)) * AG * NTOK + n;
#pragma unroll 1
        for (int a = 0; a < AG; a++) {
            const float4* ap = (const float4*)agt[a];
            float acc = 0.f;
#pragma unroll
            for (int q = 0; q < HD / 4; q++) {
                float4 av = ap[q];
                acc += av.x * kr[4 * q] + av.y * kr[4 * q + 1]
                     + av.z * kr[4 * q + 2] + av.w * kr[4 * q + 3];
            }
            sout[(size_t)a * NTOK] = acc + pb[(size_t)a * NTOK + n];
        }
    }
}

// ---------------- stage 1: fused softmax + agent_v = softmax(scores) @ v ----------------
__global__ __launch_bounds__(256) void s1_av()
{
    const int b = blockIdx.x / NH, h = blockIdx.x % NH;
    __shared__ float sv[64][HD];
    __shared__ float sp[AG][64];
    __shared__ float smx[AG], sinv[AG];
    const int tid = threadIdx.x;
    const int wid = tid >> 5, lane = tid & 31;
    const int d  = tid & 63;
    const int a0 = tid >> 6;

    const size_t pbase = ((size_t)(b * NH + h)) * AG * NTOK;
    const float* S = g_s1 + pbase;

    // phase 1: per-agent max & sum (warp per agent)
    for (int a = wid; a < AG; a += 8) {
        const float* row = S + (size_t)a * NTOK;
        float mx = -1e30f;
        for (int n = lane; n < NTOK; n += 32) mx = fmaxf(mx, row[n]);
#pragma unroll
        for (int o = 16; o > 0; o >>= 1)
            mx = fmaxf(mx, __shfl_xor_sync(0xFFFFFFFFu, mx, o));
        float sm = 0.f;
        for (int n = lane; n < NTOK; n += 32) sm += expf(row[n] - mx);
#pragma unroll
        for (int o = 16; o > 0; o >>= 1)
            sm += __shfl_xor_sync(0xFFFFFFFFu, sm, o);
        if (lane == 0) { smx[a] = mx; sinv[a] = 1.f / sm; }
    }
    __syncthreads();

    float acc[13];
#pragma unroll
    for (int i = 0; i < 13; i++) acc[i] = 0.f;

    for (int n0 = 0; n0 < NTOK; n0 += 64) {
        int nt = min(64, NTOK - n0);
        __syncthreads();
        for (int i = tid; i < nt * HD; i += 256) {
            int nn = i >> 6, dd = i & 63;
            sv[nn][dd] = g_qkv[((size_t)(b * NTOK + n0 + nn)) * (3 * CH) + 2 * CH + h * HD + dd];
        }
        for (int i = tid; i < AG * 64; i += 256) {
            int a = i >> 6, nn = i & 63;
            if (nn < nt)
                sp[a][nn] = expf(S[(size_t)a * NTOK + n0 + nn] - smx[a]);
        }
        __syncthreads();
        for (int nn = 0; nn < nt; nn++) {
            float vv = sv[nn][d];
#pragma unroll
            for (int i = 0; i < 13; i++) {
                int a = a0 + 4 * i;
                if (a < AG) acc[i] += sp[a][nn] * vv;
            }
        }
    }
#pragma unroll
    for (int i = 0; i < 13; i++) {
        int a = a0 + 4 * i;
        if (a < AG)
            g_agentv[((size_t)(b * NH + h) * AG + a) * HD + d] = acc[i] * sinv[a];
    }
}

// ---------------- stage 2 fused ----------------
__global__ __launch_bounds__(256) void stage2(const float* __restrict__ agent)
{
    const int h = blockIdx.y, b = blockIdx.z;
    __shared__ __align__(16) float agt[AG][HD];
    __shared__ __align__(16) float sv[AG][HD];
    for (int i = threadIdx.x; i < AG * HD; i += 256) {
        int a = i / HD, d = i % HD;
        agt[a][d] = agent[((size_t)b * AG + a) * CH + h * HD + d] * SCALE;
        sv[a][d]  = g_agentv[((size_t)(b * NH + h) * AG + a) * HD + d];
    }
    __syncthreads();

    const int n = blockIdx.x * 256 + threadIdx.x;
    if (n >= NTOK) return;

    float qr[HD];
    const float* qp = g_qkv + ((size_t)(b * NTOK + n)) * (3 * CH) + h * HD;
#pragma unroll
    for (int dd = 0; dd < HD; dd += 4) {
        float4 t = *(const float4*)(qp + dd);
        qr[dd] = t.x; qr[dd + 1] = t.y; qr[dd + 2] = t.z; qr[dd + 3] = t.w;
    }

    const float* pb = g_pos2 + ((size_t)h * NTOK + n) * AG;
    float sc[AG];
    float mx = -1e30f;
#pragma unroll 1
    for (int a = 0; a < AG; a++) {
        const float4* ap = (const float4*)agt[a];
        float acc = 0.f;
#pragma unroll
        for (int q = 0; q < HD / 4; q++) {
            float4 av = ap[q];
            acc += av.x * qr[4 * q] + av.y * qr[4 * q + 1]
                 + av.z * qr[4 * q + 2] + av.w * qr[4 * q + 3];
        }
        sc[a] = acc + pb[a];
        mx = fmaxf(mx, sc[a]);
    }
    float sum = 0.f;
#pragma unroll
    for (int a = 0; a < AG; a++) {
        float e = expf(sc[a] - mx);
        sc[a] = e; sum += e;
    }
    float inv = 1.f / sum;
#pragma unroll
    for (int a = 0; a < AG; a++) sc[a] *= inv;

    float od[HD];
#pragma unroll
    for (int dd = 0; dd < HD; dd++) od[dd] = 0.f;
#pragma unroll 1
    for (int a = 0; a < AG; a++) {
        float w = sc[a];
        const float4* vp = (const float4*)sv[a];
#pragma unroll
        for (int q = 0; q < HD / 4; q++) {
            float4 t = vp[q];
            od[4 * q]     += w * t.x; od[4 * q + 1] += w * t.y;
            od[4 * q + 2] += w * t.z; od[4 * q + 3] += w * t.w;
        }
    }
    float* op = g_attn + ((size_t)(b * NTOK + n)) * CH + h * HD;
#pragma unroll
    for (int dd = 0; dd < HD; dd += 4) {
        float4 t;
        t.x = od[dd]; t.y = od[dd + 1]; t.z = od[dd + 2]; t.w = od[dd + 3];
        *(float4*)(op + dd) = t;
    }
}

// ---------------- fused: depthwise conv add + three-term split into g_as ----------------
__global__ __launch_bounds__(256) void dwc_split(
    const float* __restrict__ w, const float* __restrict__ bias)
{
    const int t = blockIdx.x;          // 0..784 token index
    const int b = blockIdx.y;
    const float* src = g_attn + ((size_t)(b * NTOK + t)) * CH;
    __nv_bfloat16* dst = g_as + ((size_t)(b * NTOK + t)) * KT;

    if (t == 0) {
        for (int c = threadIdx.x; c < CH; c += 256) {
            float v = src[c];
            __nv_bfloat16 hi = __float2bfloat16(v);
            __nv_bfloat16 lo = __float2bfloat16(v - __bfloat162float(hi));
            dst[3 * c] = hi; dst[3 * c + 1] = lo; dst[3 * c + 2] = hi;
        }
        return;
    }
    const int ti = t - 1;
    const int r = ti / WIN, cc = ti % WIN;
    for (int c = threadIdx.x; c < CH; c += 256) {
        float acc = bias[c] + src[c];
#pragma unroll
        for (int ky = 0; ky < 3; ky++) {
            int rr = r + ky - 1;
            if (rr < 0 || rr >= WIN) continue;
#pragma unroll
            for (int kx = 0; kx < 3; kx++) {
                int c2 = cc + kx - 1;
                if (c2 < 0 || c2 >= WIN) continue;
                acc += w[(ky * 3 + kx) * CH + c]
                     * g_qkv[((size_t)(b * NTOK + 1 + rr * WIN + c2)) * (3 * CH) + 2 * CH + c];
            }
        }
        __nv_bfloat16 hi = __float2bfloat16(acc);
        __nv_bfloat16 lo = __float2bfloat16(acc - __bfloat162float(hi));
        dst[3 * c] = hi; dst[3 * c + 1] = lo; dst[3 * c + 2] = hi;
    }
}

// ---------------- launch ----------------
extern "C" void kernel_launch(void* const* d_in, const int* in_sizes, int n_in,
                              void* d_out, int out_size)
{
    const float* x      = (const float*)d_in[0];
    const float* w_qkv  = (const float*)d_in[1];
    const float* w_proj = (const float*)d_in[2];
    const float* b_proj = (const float*)d_in[3];
    const float* dwc_w  = (const float*)d_in[4];
    const float* dwc_b  = (const float*)d_in[5];
    const float* an_b   = (const float*)d_in[6];
    const float* ah_b   = (const float*)d_in[7];
    const float* aw_b   = (const float*)d_in[8];
    const float* na_b   = (const float*)d_in[9];
    const float* ha_b   = (const float*)d_in[10];
    const float* wa_b   = (const float*)d_in[11];
    const float* ac_b   = (const float*)d_in[12];
    const float* ca_b   = (const float*)d_in[13];
    float* out = (float*)d_out;

    float *p_qkv, *p_agent, *p_attn;
    cudaGetSymbolAddress((void**)&p_qkv, g_qkv);
    cudaGetSymbolAddress((void**)&p_agent, g_agent);
    cudaGetSymbolAddress((void**)&p_attn, g_attn);
    __nv_bfloat16 *p_xs, *p_as, *p_wqs, *p_wps;
    cudaGetSymbolAddress((void**)&p_xs, g_xs);
    cudaGetSymbolAddress((void**)&p_as, g_as);
    cudaGetSymbolAddress((void**)&p_wqs, g_wqs);
    cudaGetSymbolAddress((void**)&p_wps, g_wps);

    cudaFuncSetAttribute(gemm_mma, cudaFuncAttributeMaxDynamicSharedMemorySize,
                         GEMM_DSM);

    const int M = BATCH * NTOK;              // 50240
    const int MTILES = (M + 127) / 128;      // 393

    // 0) three-term bf16 splits of x and weights
    const int x8 = M * CH / 8;
    split3_a<<<(x8 + 255) / 256, 256>>>(x, p_xs, x8);
    const int wq8 = 3 * CH * CH / 8;
    split3_w<<<(wq8 + 255) / 256, 256>>>(w_qkv, p_wqs, wq8);
    const int wp8 = CH * CH / 8;
    split3_w<<<(wp8 + 255) / 256, 256>>>(w_proj, p_wps, wp8);

    // 1) QKV GEMM on tensor cores (mma.sync, 128x128 tiles, KC=64, 3-stage)
    gemm_mma<<<MTILES * (3 * CH / 128), 256, GEMM_DSM>>>(
        p_xs, p_wqs, nullptr, p_qkv, M, 3 * CH);

    // 2) agent pooling
    pool_agent<<<dim3(AG, BATCH), 256>>>(p_agent);

    // 3/4) position biases
    build_pos1<<<NH * AG, 256>>>(an_b, ah_b, aw_b, ac_b);
    build_pos2<<<dim3(NTOK, NH), 64>>>(na_b, ha_b, wa_b, ca_b);

    // 5) stage-1 scores, fused softmax+AV (high-occupancy pair)
    s1_scores<<<BATCH * NH, 256>>>(p_agent);
    s1_av<<<BATCH * NH, 256>>>();

    // 6) stage-2 fused attention
    stage2<<<dim3((NTOK + 255) / 256, NH, BATCH), 256>>>(p_agent);

    // 7) depthwise conv add fused with proj-input split
    dwc_split<<<dim3(NTOK, BATCH), 256>>>(dwc_w, dwc_b);

    // 8) output projection on tensor cores
    gemm_mma<<<MTILES * (CH / 128), 256, GEMM_DSM>>>(
        p_as, p_wps, b_proj, out, M, CH);
}